// round 5
// baseline (speedup 1.0000x reference)
#include <cuda_runtime.h>
#include <math.h>

#define Bn   64
#define Sn   128
#define Vn   32000
#define En   256
#define EHn  512
#define Hn   512
#define An   256
#define KFC  1280   // H + Eh + E
#define G3   1536   // 3*H

typedef unsigned long long u64;

// ---- packed f32x2 helpers (Blackwell paired fp32 pipe; PTX-only) ----
__device__ __forceinline__ u64 ffma2(u64 a, u64 b, u64 c) {
    u64 d;
    asm("fma.rn.f32x2 %0, %1, %2, %3;" : "=l"(d) : "l"(a), "l"(b), "l"(c));
    return d;
}
__device__ __forceinline__ u64 add2(u64 a, u64 b) {
    u64 d;
    asm("add.rn.f32x2 %0, %1, %2;" : "=l"(d) : "l"(a), "l"(b));
    return d;
}
__device__ __forceinline__ u64 pack2(float v) {
    u64 d; asm("mov.b64 %0, {%1, %1};" : "=l"(d) : "f"(v)); return d;
}
__device__ __forceinline__ float2 unpack2(u64 v) {
    float2 f; asm("mov.b64 {%0, %1}, %2;" : "=f"(f.x), "=f"(f.y) : "l"(v)); return f;
}

// ---- scratch (allocation-free: __device__ globals) ----
__device__ float g_embedded[Bn*En];
__device__ float g_dproj[Bn*An];
__device__ float g_scores[Bn*Sn];
__device__ float g_context[Bn*EHn];
__device__ float g_gx[Bn*G3];
__device__ float g_gh[Bn*G3];
__device__ float g_actT[KFC*Bn];   // TRANSPOSED activations: [k][b], k in [nh(512)|ctx(512)|emb(256)]

// ============================================================
// K0: embedded = emb[tgt];  dproj = hidden @ Wa_dec + ba
// grid 64 (b), 256 threads (a index)
// ============================================================
__global__ void k0_embed_dproj(const int* __restrict__ tgt,
                               const float* __restrict__ hidden,
                               const float* __restrict__ emb,
                               const float* __restrict__ Wa_dec,
                               const float* __restrict__ ba) {
    int b = blockIdx.x;
    int a = threadIdx.x;
    __shared__ float h_s[Hn];
    for (int i = threadIdx.x; i < Hn; i += 256) h_s[i] = hidden[b*Hn + i];

    int tok = tgt[b];
    float ev = emb[(size_t)tok*En + a];
    g_embedded[b*En + a] = ev;
    g_actT[(Hn + EHn + a)*Bn + b] = ev;   // emb rows at k = 1024..1279
    __syncthreads();

    float a0 = ba[a], a1 = 0.f, a2 = 0.f, a3 = 0.f;
    #pragma unroll 4
    for (int h = 0; h < Hn; h += 4) {
        a0 += h_s[h  ] * Wa_dec[(h  )*An + a];
        a1 += h_s[h+1] * Wa_dec[(h+1)*An + a];
        a2 += h_s[h+2] * Wa_dec[(h+2)*An + a];
        a3 += h_s[h+3] * Wa_dec[(h+3)*An + a];
    }
    g_dproj[b*An + a] = (a0 + a1) + (a2 + a3);
}

// ============================================================
// K1: energy = tanh(enc @ Wa_enc + dproj + ba);  scores = energy . v_att
// grid (2 s-chunks of 64, 64 b), 512 threads (16 warps).
// warp -> 4 s; lane -> 8 a (4 f32x2 pairs over a).
// ============================================================
__global__ __launch_bounds__(512, 1)
void k1_energy(const float* __restrict__ enc,
               const float* __restrict__ Wa_enc,
               const float* __restrict__ v_att,
               const int* __restrict__ mask) {
    int b  = blockIdx.y;
    int s0 = blockIdx.x * 64;
    int ta  = threadIdx.x & 31;    // lane: a-tile
    int wid = threadIdx.x >> 5;    // warp: 4-s tile

    __shared__ __align__(16) float w_s[32][An];     // [e_chunk][a]
    __shared__ __align__(16) float e_s[32][72];     // [e_chunk][s]  (72 floats = 288B, 16B-mult)

    u64 acc[4][4] = {};   // [s][a-pair]

    for (int e0 = 0; e0 < EHn; e0 += 32) {
        for (int i = threadIdx.x; i < 32*An; i += 512) {
            int er = i >> 8, a = i & 255;
            w_s[er][a] = Wa_enc[(e0 + er)*An + a];
        }
        for (int i = threadIdx.x; i < 32*64; i += 512) {
            int er = i >> 6, s = i & 63;                 // lanes -> s (coalesced gmem, clean STS)
            e_s[er][s] = enc[((size_t)(b*Sn + s0 + s))*EHn + e0 + er];
        }
        __syncthreads();

        #pragma unroll
        for (int er = 0; er < 32; er++) {
            const u64* wp0 = (const u64*)&w_s[er][ta*4];        // a-pairs, no pack needed
            const u64* wp1 = (const u64*)&w_s[er][128 + ta*4];
            u64 w0 = wp0[0], w1 = wp0[1], w2 = wp1[0], w3 = wp1[1];
            float4 ef = *(const float4*)&e_s[er][wid*4];
            u64 ed[4] = {pack2(ef.x), pack2(ef.y), pack2(ef.z), pack2(ef.w)};
            #pragma unroll
            for (int s = 0; s < 4; s++) {
                acc[s][0] = ffma2(ed[s], w0, acc[s][0]);
                acc[s][1] = ffma2(ed[s], w1, acc[s][1]);
                acc[s][2] = ffma2(ed[s], w2, acc[s][2]);
                acc[s][3] = ffma2(ed[s], w3, acc[s][3]);
            }
        }
        __syncthreads();
    }

    // epilogue: energy pair += dproj pair; tanh; dot with v_att; warp-reduce over a
    const u64* dq0 = (const u64*)&g_dproj[b*An + ta*4];
    const u64* dq1 = (const u64*)&g_dproj[b*An + 128 + ta*4];
    u64 dpp[4] = {dq0[0], dq0[1], dq1[0], dq1[1]};
    float vaf[8];
    #pragma unroll
    for (int c = 0; c < 4; c++) {
        vaf[2*c]   = v_att[(c < 2 ? ta*4 + 2*c     : 128 + ta*4 + 2*(c-2))];
        vaf[2*c+1] = v_att[(c < 2 ? ta*4 + 2*c + 1 : 128 + ta*4 + 2*(c-2) + 1)];
    }
    #pragma unroll
    for (int s = 0; s < 4; s++) {
        float p = 0.f;
        #pragma unroll
        for (int c = 0; c < 4; c++) {
            float2 u = unpack2(add2(acc[s][c], dpp[c]));
            p += tanhf(u.x)*vaf[2*c] + tanhf(u.y)*vaf[2*c+1];
        }
        #pragma unroll
        for (int o = 16; o > 0; o >>= 1) p += __shfl_xor_sync(0xffffffffu, p, o);
        if (ta == 0) {
            int sg = s0 + wid*4 + s;
            g_scores[b*Sn + sg] = mask[b*Sn + sg] ? p : -1e9f;
        }
    }
}

// ============================================================
// K2: softmax over S, context = attn @ enc.  grid 64 (b), 512 threads.
// ============================================================
__global__ __launch_bounds__(512, 1)
void k2_softmax_ctx(const float* __restrict__ enc,
                    float* __restrict__ out_attn) {
    int b = blockIdx.x;
    int t = threadIdx.x;
    int lane = t & 31, wid = t >> 5;
    int ts = t & 127;                      // replicated score index
    __shared__ float at_s[Sn];
    __shared__ float redm[16], reds[16];

    float v = g_scores[b*Sn + ts];
    float m = v;
    #pragma unroll
    for (int o = 16; o > 0; o >>= 1) m = fmaxf(m, __shfl_xor_sync(0xffffffffu, m, o));
    if (lane == 0) redm[wid] = m;
    __syncthreads();
    m = fmaxf(fmaxf(redm[0], redm[1]), fmaxf(redm[2], redm[3]));

    float ex = __expf(v - m);
    float sm = ex;
    #pragma unroll
    for (int o = 16; o > 0; o >>= 1) sm += __shfl_xor_sync(0xffffffffu, sm, o);
    if (lane == 0) reds[wid] = sm;
    __syncthreads();
    float tot = reds[0] + reds[1] + reds[2] + reds[3];

    float at = ex / tot;
    if (t < 128) {
        at_s[t] = at;
        if (out_attn) out_attn[b*Sn + t] = at;
    }
    __syncthreads();

    int h = t;                             // 512 threads = EHn
    float c0 = 0.f, c1 = 0.f, c2 = 0.f, c3 = 0.f;
    #pragma unroll 4
    for (int s = 0; s < Sn; s += 4) {
        c0 += at_s[s  ] * enc[((size_t)(b*Sn + s  ))*EHn + h];
        c1 += at_s[s+1] * enc[((size_t)(b*Sn + s+1))*EHn + h];
        c2 += at_s[s+2] * enc[((size_t)(b*Sn + s+2))*EHn + h];
        c3 += at_s[s+3] * enc[((size_t)(b*Sn + s+3))*EHn + h];
    }
    float c = (c0 + c1) + (c2 + c3);
    g_context[b*EHn + h] = c;
    g_actT[(Hn + h)*Bn + b] = c;           // ctx rows at k = 512..1023
}

// ============================================================
// K3: gx = x @ W_ih^T + b_ih (K=768); gh = hidden @ W_hh^T + b_hh (K=512)
// grid (48 j-tiles of 32, 4 b-tiles of 16), 256 thr.
// lane -> j, warp -> 2 b (one f32x2 pair). k-parity split accumulators.
// ============================================================
__global__ __launch_bounds__(256, 2)
void k3_gates(const float* __restrict__ hidden,
              const float* __restrict__ W_ih, const float* __restrict__ W_hh,
              const float* __restrict__ b_ih, const float* __restrict__ b_hh) {
    int tj = threadIdx.x & 31;
    int tw = threadIdx.x >> 5;          // 0..7 -> b-pair
    int jbase = blockIdx.x*32;
    int j  = jbase + tj;
    int bbase = blockIdx.y * 16;

    __shared__ float wt[64][33];                 // [k][j]
    __shared__ float xs[64][18];                 // [k][b_local]

    u64 ax0 = 0, ax1 = 0, ah0 = 0, ah1 = 0;

    // ---- gx: K = 768 over x = [embedded(256) | context(512)] ----
    for (int kc = 0; kc < 768; kc += 64) {
        for (int f = threadIdx.x; f < 512; f += 256) {
            int jr = f >> 4, kq = (f & 15) << 2;
            float4 w = *(const float4*)&W_ih[(size_t)(jbase + jr)*768 + kc + kq];
            wt[kq][jr] = w.x; wt[kq+1][jr] = w.y; wt[kq+2][jr] = w.z; wt[kq+3][jr] = w.w;
        }
        for (int i = threadIdx.x; i < 64*16; i += 256) {
            int bb = i >> 6, k = i & 63;
            int kk = kc + k;
            xs[k][bb] = (kk < En) ? g_embedded[(bbase + bb)*En + kk]
                                  : g_context[(bbase + bb)*EHn + (kk - En)];
        }
        __syncthreads();
        #pragma unroll 8
        for (int k = 0; k < 64; k += 2) {
            u64 x0 = *(const u64*)&xs[k  ][tw*2];
            u64 x1 = *(const u64*)&xs[k+1][tw*2];
            ax0 = ffma2(x0, pack2(wt[k  ][tj]), ax0);
            ax1 = ffma2(x1, pack2(wt[k+1][tj]), ax1);
        }
        __syncthreads();
    }

    // ---- gh: K = 512 over hidden ----
    for (int kc = 0; kc < 512; kc += 64) {
        for (int f = threadIdx.x; f < 512; f += 256) {
            int jr = f >> 4, kq = (f & 15) << 2;
            float4 w = *(const float4*)&W_hh[(size_t)(jbase + jr)*512 + kc + kq];
            wt[kq][jr] = w.x; wt[kq+1][jr] = w.y; wt[kq+2][jr] = w.z; wt[kq+3][jr] = w.w;
        }
        for (int i = threadIdx.x; i < 64*16; i += 256) {
            int bb = i >> 6, k = i & 63;
            xs[k][bb] = hidden[(bbase + bb)*Hn + kc + k];
        }
        __syncthreads();
        #pragma unroll 8
        for (int k = 0; k < 64; k += 2) {
            u64 x0 = *(const u64*)&xs[k  ][tw*2];
            u64 x1 = *(const u64*)&xs[k+1][tw*2];
            ah0 = ffma2(x0, pack2(wt[k  ][tj]), ah0);
            ah1 = ffma2(x1, pack2(wt[k+1][tj]), ah1);
        }
        __syncthreads();
    }

    float bi = b_ih[j], bh = b_hh[j];
    float2 ux = unpack2(add2(ax0, ax1));
    float2 uh = unpack2(add2(ah0, ah1));
    int b0 = bbase + tw*2;
    g_gx[(b0    )*G3 + j] = ux.x + bi;
    g_gx[(b0 + 1)*G3 + j] = ux.y + bi;
    g_gh[(b0    )*G3 + j] = uh.x + bh;
    g_gh[(b0 + 1)*G3 + j] = uh.y + bh;
}

// ============================================================
// K3b: GRU combine -> new_hidden.  32768 threads.
// ============================================================
__global__ void k3b_gru(const float* __restrict__ hidden, float* __restrict__ out_h) {
    int gid = blockIdx.x*256 + threadIdx.x;
    int b = gid >> 9, i = gid & 511;
    const float* gx = g_gx + b*G3;
    const float* gh = g_gh + b*G3;
    float r = 1.f/(1.f + __expf(-(gx[i]        + gh[i])));
    float z = 1.f/(1.f + __expf(-(gx[Hn + i]   + gh[Hn + i])));
    float n = tanhf(gx[2*Hn + i] + r*gh[2*Hn + i]);
    float nh = (1.f - z)*n + z*hidden[b*Hn + i];
    g_actT[i*Bn + b] = nh;                 // nh rows at k = 0..511
    if (out_h) out_h[b*Hn + i] = nh;
}

// ============================================================
// K4: prediction = act @ W_fc + b_fc.   grid 250 (v-tiles of 128), 512 thr.
// warp -> 8 v (uniform W loads), lane -> 2 b.  Act pre-duplicated u64 in smem.
// ============================================================
__global__ __launch_bounds__(512, 2)
void k4_fc(const float* __restrict__ W_fc, const float* __restrict__ b_fc,
           float* __restrict__ out) {
    int lane = threadIdx.x & 31;
    int wid  = threadIdx.x >> 5;           // 0..15
    int v0 = blockIdx.x*128 + wid*8;

    __shared__ __align__(16) u64 asd[64][64];   // [k][b] duplicated pairs, 32KB
    u64 acc[2][4] = {};                     // [b-slot (lane / lane+32)][v-pair]

    for (int kc = 0; kc < KFC; kc += 64) {
        for (int i = threadIdx.x; i < 64*64; i += 512) {
            int k = i >> 6, bb = i & 63;                   // lanes -> bb: coalesced LDG + clean STS
            asd[k][bb] = pack2(g_actT[(kc + k)*Bn + bb]);
        }
        __syncthreads();
        #pragma unroll 4
        for (int k = 0; k < 64; k++) {
            const float* wrow = &W_fc[(size_t)(kc + k)*Vn + v0];
            ulonglong2 wa = __ldg((const ulonglong2*)wrow);        // v-pairs (w0,w1),(w2,w3)
            ulonglong2 wb = __ldg((const ulonglong2*)(wrow + 4));  // (w4,w5),(w6,w7)
            u64 a0 = asd[k][lane];
            u64 a1 = asd[k][lane + 32];
            acc[0][0] = ffma2(wa.x, a0, acc[0][0]);
            acc[0][1] = ffma2(wa.y, a0, acc[0][1]);
            acc[0][2] = ffma2(wb.x, a0, acc[0][2]);
            acc[0][3] = ffma2(wb.y, a0, acc[0][3]);
            acc[1][0] = ffma2(wa.x, a1, acc[1][0]);
            acc[1][1] = ffma2(wa.y, a1, acc[1][1]);
            acc[1][2] = ffma2(wb.x, a1, acc[1][2]);
            acc[1][3] = ffma2(wb.y, a1, acc[1][3]);
        }
        __syncthreads();
    }

    float bias[8];
    #pragma unroll
    for (int c = 0; c < 8; c++) bias[c] = b_fc[v0 + c];
    #pragma unroll
    for (int p = 0; p < 2; p++) {
        int b = lane + p*32;
        #pragma unroll
        for (int jj = 0; jj < 4; jj++) {
            float2 u = unpack2(acc[p][jj]);
            float2 o = make_float2(u.x + bias[2*jj], u.y + bias[2*jj+1]);
            *(float2*)&out[(size_t)b*Vn + v0 + 2*jj] = o;
        }
    }
}

// ============================================================
extern "C" void kernel_launch(void* const* d_in, const int* in_sizes, int n_in,
                              void* d_out, int out_size) {
    const int*   tgt    = (const int*)d_in[0];
    const float* hidden = (const float*)d_in[1];
    const float* enc    = (const float*)d_in[2];
    const int*   mask   = (const int*)d_in[3];     // bool -> int32 in harness
    const float* emb    = (const float*)d_in[4];
    const float* Wa_enc = (const float*)d_in[5];
    const float* Wa_dec = (const float*)d_in[6];
    const float* ba     = (const float*)d_in[7];
    const float* v_att  = (const float*)d_in[8];
    const float* W_ih   = (const float*)d_in[9];
    const float* W_hh   = (const float*)d_in[10];
    const float* b_ih   = (const float*)d_in[11];
    const float* b_hh   = (const float*)d_in[12];
    const float* W_fc   = (const float*)d_in[13];
    const float* b_fc   = (const float*)d_in[14];

    float* out_pred = (float*)d_out;
    float* out_h    = nullptr;
    float* out_attn = nullptr;
    if (out_size >= Bn*Vn + Bn*Hn + Bn*Sn) {
        out_h    = out_pred + (size_t)Bn*Vn;
        out_attn = out_h    + (size_t)Bn*Hn;
    }

    k0_embed_dproj<<<Bn, 256>>>(tgt, hidden, emb, Wa_dec, ba);
    k1_energy<<<dim3(2, Bn), 512>>>(enc, Wa_enc, v_att, mask);
    k2_softmax_ctx<<<Bn, 512>>>(enc, out_attn);
    k3_gates<<<dim3(48, 4), 256>>>(hidden, W_ih, W_hh, b_ih, b_hh);
    k3b_gru<<<128, 256>>>(hidden, out_h);
    k4_fc<<<250, 512>>>(W_fc, b_fc, out_pred);
}

// round 6
// speedup vs baseline: 1.6348x; 1.6348x over previous
#include <cuda_runtime.h>
#include <math.h>
#include <stdint.h>

#define Bn   64
#define Sn   128
#define Vn   32000
#define En   256
#define EHn  512
#define Hn   512
#define An   256
#define KFC  1280   // H + Eh + E
#define G3   1536   // 3*H

// ---- scratch (allocation-free: __device__ globals) ----
__device__ float g_embedded[Bn*En];
__device__ float g_dproj[Bn*An];
__device__ float g_scores[Bn*Sn];
__device__ float g_context[Bn*EHn];
__device__ float g_gx[Bn*G3];
__device__ float g_gh[Bn*G3];
__device__ float g_act[Bn*KFC];   // row-major [b][k]: [new_hidden(512) | context(512) | embedded(256)]

__device__ __forceinline__ uint32_t f2tf32(float x) {
    uint32_t r;
    asm("cvt.rna.tf32.f32 %0, %1;" : "=r"(r) : "f"(x));
    return r;
}
__device__ __forceinline__ void mma_tf32_16x8x8(float& c0, float& c1, float& c2, float& c3,
                                                uint32_t a0, uint32_t a1, uint32_t a2, uint32_t a3,
                                                uint32_t b0, uint32_t b1) {
    asm("mma.sync.aligned.m16n8k8.row.col.f32.tf32.tf32.f32 "
        "{%0,%1,%2,%3}, {%4,%5,%6,%7}, {%8,%9}, {%0,%1,%2,%3};"
        : "+f"(c0), "+f"(c1), "+f"(c2), "+f"(c3)
        : "r"(a0), "r"(a1), "r"(a2), "r"(a3), "r"(b0), "r"(b1));
}

// ============================================================
// K0: embedded = emb[tgt];  dproj = hidden @ Wa_dec + ba
// ============================================================
__global__ void k0_embed_dproj(const int* __restrict__ tgt,
                               const float* __restrict__ hidden,
                               const float* __restrict__ emb,
                               const float* __restrict__ Wa_dec,
                               const float* __restrict__ ba) {
    int b = blockIdx.x;
    int a = threadIdx.x;
    __shared__ float h_s[Hn];
    for (int i = threadIdx.x; i < Hn; i += 256) h_s[i] = hidden[b*Hn + i];

    int tok = tgt[b];
    float ev = emb[(size_t)tok*En + a];
    g_embedded[b*En + a] = ev;
    g_act[b*KFC + Hn + EHn + a] = ev;   // embedded at offset 1024
    __syncthreads();

    float a0 = ba[a], a1 = 0.f, a2 = 0.f, a3 = 0.f;
    #pragma unroll 4
    for (int h = 0; h < Hn; h += 4) {
        a0 += h_s[h  ] * Wa_dec[(h  )*An + a];
        a1 += h_s[h+1] * Wa_dec[(h+1)*An + a];
        a2 += h_s[h+2] * Wa_dec[(h+2)*An + a];
        a3 += h_s[h+3] * Wa_dec[(h+3)*An + a];
    }
    g_dproj[b*An + a] = (a0 + a1) + (a2 + a3);
}

// ============================================================
// K1: energy = tanh(enc @ Wa_enc + dproj + ba);  scores = energy . v_att
// grid (2 s-chunks, 64 b), 256 threads.  Thread tile: 8 s x 8 a.  (R3 version)
// ============================================================
__global__ __launch_bounds__(256, 1)
void k1_energy(const float* __restrict__ enc,
               const float* __restrict__ Wa_enc,
               const float* __restrict__ v_att,
               const int* __restrict__ mask) {
    int b  = blockIdx.y;
    int s0 = blockIdx.x * 64;
    int ta = threadIdx.x & 31;
    int ts = threadIdx.x >> 5;

    __shared__ float w_s[32][An];
    __shared__ float e_s[32][68];

    float acc[8][8] = {};

    for (int e0 = 0; e0 < EHn; e0 += 32) {
        for (int i = threadIdx.x; i < 32*An; i += 256) {
            int er = i >> 8, a = i & 255;
            w_s[er][a] = Wa_enc[(e0 + er)*An + a];
        }
        for (int i = threadIdx.x; i < 64*32; i += 256) {
            int s = i >> 5, er = i & 31;
            e_s[er][s] = enc[((size_t)(b*Sn + s0 + s))*EHn + e0 + er];
        }
        __syncthreads();

        #pragma unroll
        for (int er = 0; er < 32; er++) {
            float4 w0 = *(const float4*)&w_s[er][ta*4];
            float4 w1 = *(const float4*)&w_s[er][128 + ta*4];
            float4 ea = *(const float4*)&e_s[er][ts*8];
            float4 eb = *(const float4*)&e_s[er][ts*8 + 4];
            float ev[8] = {ea.x, ea.y, ea.z, ea.w, eb.x, eb.y, eb.z, eb.w};
            #pragma unroll
            for (int j = 0; j < 8; j++) {
                acc[j][0] += ev[j]*w0.x; acc[j][1] += ev[j]*w0.y;
                acc[j][2] += ev[j]*w0.z; acc[j][3] += ev[j]*w0.w;
                acc[j][4] += ev[j]*w1.x; acc[j][5] += ev[j]*w1.y;
                acc[j][6] += ev[j]*w1.z; acc[j][7] += ev[j]*w1.w;
            }
        }
        __syncthreads();
    }

    float dp[8], va[8];
    #pragma unroll
    for (int c = 0; c < 4; c++) {
        dp[c]   = g_dproj[b*An + ta*4 + c];
        dp[c+4] = g_dproj[b*An + 128 + ta*4 + c];
        va[c]   = v_att[ta*4 + c];
        va[c+4] = v_att[128 + ta*4 + c];
    }
    #pragma unroll
    for (int j = 0; j < 8; j++) {
        float p = 0.f;
        #pragma unroll
        for (int c = 0; c < 8; c++) p += tanhf(acc[j][c] + dp[c]) * va[c];
        #pragma unroll
        for (int o = 16; o > 0; o >>= 1) p += __shfl_xor_sync(0xffffffffu, p, o);
        if (ta == 0) {
            int s = s0 + ts*8 + j;
            g_scores[b*Sn + s] = mask[b*Sn + s] ? p : -1e9f;
        }
    }
}

// ============================================================
// K2: softmax over S, context = attn @ enc.  grid 64 (b), 128 threads. (R3)
// ============================================================
__global__ void k2_softmax_ctx(const float* __restrict__ enc,
                               float* __restrict__ out_attn) {
    int b = blockIdx.x;
    int t = threadIdx.x;
    __shared__ float at_s[Sn];
    __shared__ float red[4];

    float v = g_scores[b*Sn + t];
    float m = v;
    #pragma unroll
    for (int o = 16; o > 0; o >>= 1) m = fmaxf(m, __shfl_xor_sync(0xffffffffu, m, o));
    if ((t & 31) == 0) red[t >> 5] = m;
    __syncthreads();
    m = fmaxf(fmaxf(red[0], red[1]), fmaxf(red[2], red[3]));
    __syncthreads();

    float ex = __expf(v - m);
    float sm = ex;
    #pragma unroll
    for (int o = 16; o > 0; o >>= 1) sm += __shfl_xor_sync(0xffffffffu, sm, o);
    if ((t & 31) == 0) red[t >> 5] = sm;
    __syncthreads();
    float tot = red[0] + red[1] + red[2] + red[3];

    float at = ex / tot;
    at_s[t] = at;
    if (out_attn) out_attn[b*Sn + t] = at;
    __syncthreads();

    for (int h = t; h < EHn; h += 128) {
        float c = 0.f;
        #pragma unroll 8
        for (int s = 0; s < Sn; s++) c += at_s[s] * enc[((size_t)(b*Sn + s))*EHn + h];
        g_context[b*EHn + h] = c;
        g_act[b*KFC + Hn + h] = c;
    }
}

// ============================================================
// K3: gates GEMMs (R4 version: transposed-W smem staging, best measured 61us)
// ============================================================
typedef unsigned long long u64;
__device__ __forceinline__ u64 ffma2(u64 a, u64 b, u64 c) {
    u64 d; asm("fma.rn.f32x2 %0, %1, %2, %3;" : "=l"(d) : "l"(a), "l"(b), "l"(c)); return d;
}
__device__ __forceinline__ u64 pack2(float v) {
    u64 d; asm("mov.b64 %0, {%1, %1};" : "=l"(d) : "f"(v)); return d;
}
__device__ __forceinline__ float2 unpack2(u64 v) {
    float2 f; asm("mov.b64 {%0, %1}, %2;" : "=f"(f.x), "=f"(f.y) : "l"(v)); return f;
}

__global__ __launch_bounds__(256, 2)
void k3_gates(const float* __restrict__ hidden,
              const float* __restrict__ W_ih, const float* __restrict__ W_hh,
              const float* __restrict__ b_ih, const float* __restrict__ b_hh) {
    int tj = threadIdx.x & 31;
    int tb = threadIdx.x >> 5;
    int jbase = blockIdx.x*32;
    int j  = jbase + tj;
    int bbase = blockIdx.y * 32;

    __shared__ float wt[64][33];
    __shared__ __align__(16) float xs[64][36];

    u64 accx[2] = {}, acch[2] = {};

    for (int kc = 0; kc < 768; kc += 64) {
        for (int f = threadIdx.x; f < 512; f += 256) {
            int jr = f >> 4, kq = (f & 15) << 2;
            float4 w = *(const float4*)&W_ih[(size_t)(jbase + jr)*768 + kc + kq];
            wt[kq][jr] = w.x; wt[kq+1][jr] = w.y; wt[kq+2][jr] = w.z; wt[kq+3][jr] = w.w;
        }
        for (int i = threadIdx.x; i < 64*32; i += 256) {
            int bb = i >> 6, k = i & 63;
            int kk = kc + k;
            xs[k][bb] = (kk < En) ? g_embedded[(bbase + bb)*En + kk]
                                  : g_context[(bbase + bb)*EHn + (kk - En)];
        }
        __syncthreads();
        #pragma unroll 8
        for (int k = 0; k < 64; k++) {
            u64 wd = pack2(wt[k][tj]);
            const u64* xp = (const u64*)&xs[k][tb*4];
            accx[0] = ffma2(xp[0], wd, accx[0]);
            accx[1] = ffma2(xp[1], wd, accx[1]);
        }
        __syncthreads();
    }

    for (int kc = 0; kc < 512; kc += 64) {
        for (int f = threadIdx.x; f < 512; f += 256) {
            int jr = f >> 4, kq = (f & 15) << 2;
            float4 w = *(const float4*)&W_hh[(size_t)(jbase + jr)*512 + kc + kq];
            wt[kq][jr] = w.x; wt[kq+1][jr] = w.y; wt[kq+2][jr] = w.z; wt[kq+3][jr] = w.w;
        }
        for (int i = threadIdx.x; i < 64*32; i += 256) {
            int bb = i >> 6, k = i & 63;
            xs[k][bb] = hidden[(bbase + bb)*Hn + kc + k];
        }
        __syncthreads();
        #pragma unroll 8
        for (int k = 0; k < 64; k++) {
            u64 wd = pack2(wt[k][tj]);
            const u64* xp = (const u64*)&xs[k][tb*4];
            acch[0] = ffma2(xp[0], wd, acch[0]);
            acch[1] = ffma2(xp[1], wd, acch[1]);
        }
        __syncthreads();
    }

    float bi = b_ih[j], bh = b_hh[j];
    #pragma unroll
    for (int p = 0; p < 2; p++) {
        float2 ux = unpack2(accx[p]);
        float2 uh = unpack2(acch[p]);
        int b0 = bbase + tb*4 + 2*p;
        g_gx[(b0    )*G3 + j] = ux.x + bi;
        g_gx[(b0 + 1)*G3 + j] = ux.y + bi;
        g_gh[(b0    )*G3 + j] = uh.x + bh;
        g_gh[(b0 + 1)*G3 + j] = uh.y + bh;
    }
}

// ============================================================
// K3b: GRU combine -> new_hidden.
// ============================================================
__global__ void k3b_gru(const float* __restrict__ hidden, float* __restrict__ out_h) {
    int gid = blockIdx.x*256 + threadIdx.x;
    int b = gid >> 9, i = gid & 511;
    const float* gx = g_gx + b*G3;
    const float* gh = g_gh + b*G3;
    float r = 1.f/(1.f + __expf(-(gx[i]        + gh[i])));
    float z = 1.f/(1.f + __expf(-(gx[Hn + i]   + gh[Hn + i])));
    float n = tanhf(gx[2*Hn + i] + r*gh[2*Hn + i]);
    float nh = (1.f - z)*n + z*hidden[b*Hn + i];
    g_act[b*KFC + i] = nh;
    if (out_h) out_h[b*Hn + i] = nh;
}

// ============================================================
// K4: prediction = act @ W_fc + b_fc via tf32 mma.sync (m16n8k8).
// grid 125 (v-tiles of 256), 256 thr (8 warps); warp -> 32 v, M = 64 full.
// A chunk [64][36] smem (pad -> conflict-free frag LDS), B chunk [32][264].
// ============================================================
#define K4_NT   256   // v per block
#define K4_KC   32    // k chunk
#define K4_BP   264   // Bs row pad (words): bank = 8*k + n -> conflict-free
#define K4_AP   36    // As row pad: bank = 4*m + k -> conflict-free

__global__ __launch_bounds__(256, 2)
void k4_fc(const float* __restrict__ W_fc, const float* __restrict__ b_fc,
           float* __restrict__ out) {
    int lane = threadIdx.x & 31;
    int warp = threadIdx.x >> 5;      // 0..7
    int qid  = lane >> 2;             // 0..7
    int ql   = lane & 3;              // 0..3
    int vblk = blockIdx.x * K4_NT;
    int n0   = warp * 32;             // warp's v offset within tile

    __shared__ uint32_t As[64 * K4_AP];        //  9216 B
    __shared__ uint32_t Bs[K4_KC * K4_BP];     // 33792 B

    float acc[4][4][4];                        // [mi][ni][c]
    #pragma unroll
    for (int mi = 0; mi < 4; mi++)
        #pragma unroll
        for (int ni = 0; ni < 4; ni++)
            #pragma unroll
            for (int c = 0; c < 4; c++) acc[mi][ni][c] = 0.f;

    for (int kc = 0; kc < KFC; kc += K4_KC) {
        // ---- fill A chunk: 64 x 32, coalesced LDG.32 ----
        #pragma unroll
        for (int r = 0; r < 8; r++) {
            int idx = threadIdx.x + 256*r;        // 0..2047
            int bb = idx >> 5, kf = idx & 31;
            As[bb*K4_AP + kf] = f2tf32(g_act[bb*KFC + kc + kf]);
        }
        // ---- fill B chunk: 32 x 256, coalesced LDG.128 ----
        #pragma unroll
        for (int r = 0; r < 8; r++) {
            int idx = threadIdx.x + 256*r;        // float4 index, 0..2047
            int row = idx >> 6, c4 = (idx & 63) << 2;
            float4 w = __ldg((const float4*)&W_fc[(size_t)(kc + row)*Vn + vblk + c4]);
            uint32_t* dst = &Bs[row*K4_BP + c4];
            dst[0] = f2tf32(w.x); dst[1] = f2tf32(w.y);
            dst[2] = f2tf32(w.z); dst[3] = f2tf32(w.w);
        }
        __syncthreads();

        // ---- compute: 4 k8-steps ----
        #pragma unroll
        for (int kk = 0; kk < K4_KC; kk += 8) {
            uint32_t af[4][4];
            #pragma unroll
            for (int mi = 0; mi < 4; mi++) {
                int m0 = mi*16 + qid;
                af[mi][0] = As[(m0    )*K4_AP + kk + ql    ];
                af[mi][1] = As[(m0 + 8)*K4_AP + kk + ql    ];
                af[mi][2] = As[(m0    )*K4_AP + kk + ql + 4];
                af[mi][3] = As[(m0 + 8)*K4_AP + kk + ql + 4];
            }
            #pragma unroll
            for (int ni = 0; ni < 4; ni++) {
                int nn = n0 + ni*8 + qid;
                uint32_t b0 = Bs[(kk + ql    )*K4_BP + nn];
                uint32_t b1 = Bs[(kk + ql + 4)*K4_BP + nn];
                #pragma unroll
                for (int mi = 0; mi < 4; mi++) {
                    mma_tf32_16x8x8(acc[mi][ni][0], acc[mi][ni][1], acc[mi][ni][2], acc[mi][ni][3],
                                    af[mi][0], af[mi][1], af[mi][2], af[mi][3], b0, b1);
                }
            }
        }
        __syncthreads();
    }

    // ---- epilogue: bias + store.  c0,c1: row=qid, cols 2*ql,2*ql+1; c2,c3: row+8 ----
    #pragma unroll
    for (int ni = 0; ni < 4; ni++) {
        int v = vblk + n0 + ni*8 + 2*ql;
        float bx = b_fc[v], by = b_fc[v + 1];
        #pragma unroll
        for (int mi = 0; mi < 4; mi++) {
            int row0 = mi*16 + qid;
            float2 o0 = make_float2(acc[mi][ni][0] + bx, acc[mi][ni][1] + by);
            float2 o1 = make_float2(acc[mi][ni][2] + bx, acc[mi][ni][3] + by);
            *(float2*)&out[(size_t)(row0    )*Vn + v] = o0;
            *(float2*)&out[(size_t)(row0 + 8)*Vn + v] = o1;
        }
    }
}

// ============================================================
extern "C" void kernel_launch(void* const* d_in, const int* in_sizes, int n_in,
                              void* d_out, int out_size) {
    const int*   tgt    = (const int*)d_in[0];
    const float* hidden = (const float*)d_in[1];
    const float* enc    = (const float*)d_in[2];
    const int*   mask   = (const int*)d_in[3];     // bool -> int32 in harness
    const float* emb    = (const float*)d_in[4];
    const float* Wa_enc = (const float*)d_in[5];
    const float* Wa_dec = (const float*)d_in[6];
    const float* ba     = (const float*)d_in[7];
    const float* v_att  = (const float*)d_in[8];
    const float* W_ih   = (const float*)d_in[9];
    const float* W_hh   = (const float*)d_in[10];
    const float* b_ih   = (const float*)d_in[11];
    const float* b_hh   = (const float*)d_in[12];
    const float* W_fc   = (const float*)d_in[13];
    const float* b_fc   = (const float*)d_in[14];

    float* out_pred = (float*)d_out;
    float* out_h    = nullptr;
    float* out_attn = nullptr;
    if (out_size >= Bn*Vn + Bn*Hn + Bn*Sn) {
        out_h    = out_pred + (size_t)Bn*Vn;
        out_attn = out_h    + (size_t)Bn*Hn;
    }

    k0_embed_dproj<<<Bn, 256>>>(tgt, hidden, emb, Wa_dec, ba);
    k1_energy<<<dim3(2, Bn), 256>>>(enc, Wa_enc, v_att, mask);
    k2_softmax_ctx<<<Bn, 128>>>(enc, out_attn);
    k3_gates<<<dim3(48, 2), 256>>>(hidden, W_ih, W_hh, b_ih, b_hh);
    k3b_gru<<<128, 256>>>(hidden, out_h);
    k4_fc<<<125, 256>>>(W_fc, b_fc, out_pred);
}

// round 9
// speedup vs baseline: 2.2111x; 1.3525x over previous
#include <cuda_runtime.h>
#include <math.h>
#include <stdint.h>

#define Bn   64
#define Sn   128
#define Vn   32000
#define En   256
#define EHn  512
#define Hn   512
#define An   256
#define KFC  1280   // H + Eh + E
#define G3   1536   // 3*H

// ---- scratch (allocation-free: __device__ globals) ----
__device__ float g_embedded[Bn*En];
__device__ float g_dproj[Bn*An];
__device__ float g_scores[Bn*Sn];
__device__ float g_context[Bn*EHn];
__device__ float g_gx[Bn*G3];
__device__ float g_gh[Bn*G3];
__device__ float g_act[Bn*KFC];   // row-major [b][k]: [new_hidden(512) | context(512) | embedded(256)]

__device__ __forceinline__ uint32_t f2tf32(float x) {
    uint32_t r;
    asm("cvt.rna.tf32.f32 %0, %1;" : "=r"(r) : "f"(x));
    return r;
}
__device__ __forceinline__ void mma_tf32_16x8x8(float& c0, float& c1, float& c2, float& c3,
                                                uint32_t a0, uint32_t a1, uint32_t a2, uint32_t a3,
                                                uint32_t b0, uint32_t b1) {
    asm("mma.sync.aligned.m16n8k8.row.col.f32.tf32.tf32.f32 "
        "{%0,%1,%2,%3}, {%4,%5,%6,%7}, {%8,%9}, {%0,%1,%2,%3};"
        : "+f"(c0), "+f"(c1), "+f"(c2), "+f"(c3)
        : "r"(a0), "r"(a1), "r"(a2), "r"(a3), "r"(b0), "r"(b1));
}

// ============================================================
// K0: embedded = emb[tgt];  dproj = hidden @ Wa_dec + ba
// ============================================================
__global__ void k0_embed_dproj(const int* __restrict__ tgt,
                               const float* __restrict__ hidden,
                               const float* __restrict__ emb,
                               const float* __restrict__ Wa_dec,
                               const float* __restrict__ ba) {
    int b = blockIdx.x;
    int a = threadIdx.x;
    __shared__ float h_s[Hn];
    for (int i = threadIdx.x; i < Hn; i += 256) h_s[i] = hidden[b*Hn + i];

    int tok = tgt[b];
    float ev = emb[(size_t)tok*En + a];
    g_embedded[b*En + a] = ev;
    g_act[b*KFC + Hn + EHn + a] = ev;   // embedded at offset 1024
    __syncthreads();

    float a0 = ba[a], a1 = 0.f, a2 = 0.f, a3 = 0.f;
    #pragma unroll 4
    for (int h = 0; h < Hn; h += 4) {
        a0 += h_s[h  ] * Wa_dec[(h  )*An + a];
        a1 += h_s[h+1] * Wa_dec[(h+1)*An + a];
        a2 += h_s[h+2] * Wa_dec[(h+2)*An + a];
        a3 += h_s[h+3] * Wa_dec[(h+3)*An + a];
    }
    g_dproj[b*An + a] = (a0 + a1) + (a2 + a3);
}

// ============================================================
// K1: energy = tanh(enc@Wa_enc + dproj);  scores = energy . v_att  [tf32 MMA]
// grid (2 s-halves, 64 b), 256 thr (8 warps).  M=64 (s), N=256 (a), K=512.
// ============================================================
#define K1_KC 32
#define K1_AP 36
#define K1_BP 264

__global__ __launch_bounds__(256, 1)
void k1_energy(const float* __restrict__ enc,
               const float* __restrict__ Wa_enc,
               const float* __restrict__ v_att,
               const int* __restrict__ mask) {
    int b  = blockIdx.y;
    int s0 = blockIdx.x * 64;
    int lane = threadIdx.x & 31;
    int warp = threadIdx.x >> 5;
    int qid = lane >> 2, ql = lane & 3;
    int n0 = warp * 32;

    __shared__ uint32_t As[64 * K1_AP];
    __shared__ uint32_t Bs[K1_KC * K1_BP];
    __shared__ float red[64][8];

    float acc[4][4][4];
    #pragma unroll
    for (int mi = 0; mi < 4; mi++)
        #pragma unroll
        for (int ni = 0; ni < 4; ni++)
            #pragma unroll
            for (int c = 0; c < 4; c++) acc[mi][ni][c] = 0.f;

    for (int kc = 0; kc < EHn; kc += K1_KC) {
        #pragma unroll
        for (int r = 0; r < 8; r++) {
            int idx = threadIdx.x + 256*r;
            int m = idx >> 5, kf = idx & 31;
            As[m*K1_AP + kf] = f2tf32(enc[((size_t)(b*Sn + s0 + m))*EHn + kc + kf]);
        }
        #pragma unroll
        for (int r = 0; r < 8; r++) {
            int idx = threadIdx.x + 256*r;
            int row = idx >> 6, c4 = (idx & 63) << 2;
            float4 w = __ldg((const float4*)&Wa_enc[(size_t)(kc + row)*An + c4]);
            uint32_t* dst = &Bs[row*K1_BP + c4];
            dst[0] = f2tf32(w.x); dst[1] = f2tf32(w.y);
            dst[2] = f2tf32(w.z); dst[3] = f2tf32(w.w);
        }
        __syncthreads();

        #pragma unroll
        for (int kk = 0; kk < K1_KC; kk += 8) {
            uint32_t af[4][4];
            #pragma unroll
            for (int mi = 0; mi < 4; mi++) {
                int m0 = mi*16 + qid;
                af[mi][0] = As[(m0    )*K1_AP + kk + ql    ];
                af[mi][1] = As[(m0 + 8)*K1_AP + kk + ql    ];
                af[mi][2] = As[(m0    )*K1_AP + kk + ql + 4];
                af[mi][3] = As[(m0 + 8)*K1_AP + kk + ql + 4];
            }
            #pragma unroll
            for (int ni = 0; ni < 4; ni++) {
                int nn = n0 + ni*8 + qid;
                uint32_t b0 = Bs[(kk + ql    )*K1_BP + nn];
                uint32_t b1 = Bs[(kk + ql + 4)*K1_BP + nn];
                #pragma unroll
                for (int mi = 0; mi < 4; mi++)
                    mma_tf32_16x8x8(acc[mi][ni][0], acc[mi][ni][1], acc[mi][ni][2], acc[mi][ni][3],
                                    af[mi][0], af[mi][1], af[mi][2], af[mi][3], b0, b1);
            }
        }
        __syncthreads();
    }

    // epilogue: tanh(acc + dproj) . v_att, reduce over a
    float part[4][2] = {};
    #pragma unroll
    for (int ni = 0; ni < 4; ni++) {
        int col = n0 + ni*8 + 2*ql;
        float2 dp = *(const float2*)&g_dproj[b*An + col];
        float2 va = *(const float2*)&v_att[col];
        #pragma unroll
        for (int mi = 0; mi < 4; mi++) {
            part[mi][0] += tanhf(acc[mi][ni][0] + dp.x)*va.x + tanhf(acc[mi][ni][1] + dp.y)*va.y;
            part[mi][1] += tanhf(acc[mi][ni][2] + dp.x)*va.x + tanhf(acc[mi][ni][3] + dp.y)*va.y;
        }
    }
    #pragma unroll
    for (int mi = 0; mi < 4; mi++) {
        #pragma unroll
        for (int h = 0; h < 2; h++) {
            float p = part[mi][h];
            p += __shfl_xor_sync(0xffffffffu, p, 1);
            p += __shfl_xor_sync(0xffffffffu, p, 2);
            if (ql == 0) red[mi*16 + h*8 + qid][warp] = p;
        }
    }
    __syncthreads();
    if (threadIdx.x < 64) {
        int row = threadIdx.x;
        float s = 0.f;
        #pragma unroll
        for (int w = 0; w < 8; w++) s += red[row][w];
        int sg = s0 + row;
        g_scores[b*Sn + sg] = mask[b*Sn + sg] ? s : -1e9f;
    }
}

// ============================================================
// K2: softmax over S, context = attn @ enc.  grid 64 (b), 128 threads.
// ============================================================
__global__ void k2_softmax_ctx(const float* __restrict__ enc,
                               float* __restrict__ out_attn) {
    int b = blockIdx.x;
    int t = threadIdx.x;
    __shared__ float at_s[Sn];
    __shared__ float red[4];

    float v = g_scores[b*Sn + t];
    float m = v;
    #pragma unroll
    for (int o = 16; o > 0; o >>= 1) m = fmaxf(m, __shfl_xor_sync(0xffffffffu, m, o));
    if ((t & 31) == 0) red[t >> 5] = m;
    __syncthreads();
    m = fmaxf(fmaxf(red[0], red[1]), fmaxf(red[2], red[3]));
    __syncthreads();

    float ex = __expf(v - m);
    float sm = ex;
    #pragma unroll
    for (int o = 16; o > 0; o >>= 1) sm += __shfl_xor_sync(0xffffffffu, sm, o);
    if ((t & 31) == 0) red[t >> 5] = sm;
    __syncthreads();
    float tot = red[0] + red[1] + red[2] + red[3];

    float at = ex / tot;
    at_s[t] = at;
    if (out_attn) out_attn[b*Sn + t] = at;
    __syncthreads();

    for (int h = t; h < EHn; h += 128) {
        float c = 0.f;
        #pragma unroll 8
        for (int s = 0; s < Sn; s++) c += at_s[s] * enc[((size_t)(b*Sn + s))*EHn + h];
        g_context[b*EHn + h] = c;
        g_act[b*KFC + Hn + h] = c;
    }
}

// ============================================================
// K3: gx = x@W_ih^T + b_ih (K=768); gh = hidden@W_hh^T + b_hh (K=512)  [tf32 MMA]
// grid 24 (j-tiles of 64), 256 thr (8 warps, n8 each).  M=64 (b).
// ============================================================
#define K3_KC 32
#define K3_P  36

__global__ __launch_bounds__(256, 2)
void k3_gates(const float* __restrict__ hidden,
              const float* __restrict__ W_ih, const float* __restrict__ W_hh,
              const float* __restrict__ b_ih, const float* __restrict__ b_hh) {
    int lane = threadIdx.x & 31;
    int warp = threadIdx.x >> 5;
    int qid = lane >> 2, ql = lane & 3;
    int jbase = blockIdx.x * 64;
    int n0 = warp * 8;

    __shared__ uint32_t As[64 * K3_P];
    __shared__ uint32_t Bs[64 * K3_P];

    // ---------- phase 1: gx over K=768, x = [embedded | context] ----------
    {
        float acc[4][4];
        #pragma unroll
        for (int mi = 0; mi < 4; mi++)
            #pragma unroll
            for (int c = 0; c < 4; c++) acc[mi][c] = 0.f;

        for (int kc = 0; kc < 768; kc += K3_KC) {
            #pragma unroll
            for (int r = 0; r < 8; r++) {
                int idx = threadIdx.x + 256*r;
                int m = idx >> 5, kf = idx & 31;
                int kk = kc + kf;
                float v = (kk < En) ? g_embedded[m*En + kk] : g_context[m*EHn + (kk - En)];
                As[m*K3_P + kf] = f2tf32(v);
            }
            #pragma unroll
            for (int r = 0; r < 2; r++) {
                int idx = threadIdx.x + 256*r;
                int j = idx >> 3, k4 = (idx & 7) << 2;
                float4 w = __ldg((const float4*)&W_ih[(size_t)(jbase + j)*768 + kc + k4]);
                uint32_t* dst = &Bs[j*K3_P + k4];
                dst[0] = f2tf32(w.x); dst[1] = f2tf32(w.y);
                dst[2] = f2tf32(w.z); dst[3] = f2tf32(w.w);
            }
            __syncthreads();
            #pragma unroll
            for (int kk = 0; kk < K3_KC; kk += 8) {
                int nn = n0 + qid;
                uint32_t b0 = Bs[nn*K3_P + kk + ql    ];
                uint32_t b1 = Bs[nn*K3_P + kk + ql + 4];
                #pragma unroll
                for (int mi = 0; mi < 4; mi++) {
                    int m0 = mi*16 + qid;
                    uint32_t a0 = As[(m0    )*K3_P + kk + ql    ];
                    uint32_t a1 = As[(m0 + 8)*K3_P + kk + ql    ];
                    uint32_t a2 = As[(m0    )*K3_P + kk + ql + 4];
                    uint32_t a3 = As[(m0 + 8)*K3_P + kk + ql + 4];
                    mma_tf32_16x8x8(acc[mi][0], acc[mi][1], acc[mi][2], acc[mi][3],
                                    a0, a1, a2, a3, b0, b1);
                }
            }
            __syncthreads();
        }
        int j = jbase + n0 + 2*ql;
        float bx = b_ih[j], by = b_ih[j + 1];
        #pragma unroll
        for (int mi = 0; mi < 4; mi++) {
            int r0 = mi*16 + qid;
            *(float2*)&g_gx[(size_t)(r0    )*G3 + j] = make_float2(acc[mi][0] + bx, acc[mi][1] + by);
            *(float2*)&g_gx[(size_t)(r0 + 8)*G3 + j] = make_float2(acc[mi][2] + bx, acc[mi][3] + by);
        }
    }
    __syncthreads();

    // ---------- phase 2: gh over K=512, hidden ----------
    {
        float acc[4][4];
        #pragma unroll
        for (int mi = 0; mi < 4; mi++)
            #pragma unroll
            for (int c = 0; c < 4; c++) acc[mi][c] = 0.f;

        for (int kc = 0; kc < 512; kc += K3_KC) {
            #pragma unroll
            for (int r = 0; r < 8; r++) {
                int idx = threadIdx.x + 256*r;
                int m = idx >> 5, kf = idx & 31;
                As[m*K3_P + kf] = f2tf32(hidden[m*Hn + kc + kf]);
            }
            #pragma unroll
            for (int r = 0; r < 2; r++) {
                int idx = threadIdx.x + 256*r;
                int j = idx >> 3, k4 = (idx & 7) << 2;
                float4 w = __ldg((const float4*)&W_hh[(size_t)(jbase + j)*512 + kc + k4]);
                uint32_t* dst = &Bs[j*K3_P + k4];
                dst[0] = f2tf32(w.x); dst[1] = f2tf32(w.y);
                dst[2] = f2tf32(w.z); dst[3] = f2tf32(w.w);
            }
            __syncthreads();
            #pragma unroll
            for (int kk = 0; kk < K3_KC; kk += 8) {
                int nn = n0 + qid;
                uint32_t b0 = Bs[nn*K3_P + kk + ql    ];
                uint32_t b1 = Bs[nn*K3_P + kk + ql + 4];
                #pragma unroll
                for (int mi = 0; mi < 4; mi++) {
                    int m0 = mi*16 + qid;
                    uint32_t a0 = As[(m0    )*K3_P + kk + ql    ];
                    uint32_t a1 = As[(m0 + 8)*K3_P + kk + ql    ];
                    uint32_t a2 = As[(m0    )*K3_P + kk + ql + 4];
                    uint32_t a3 = As[(m0 + 8)*K3_P + kk + ql + 4];
                    mma_tf32_16x8x8(acc[mi][0], acc[mi][1], acc[mi][2], acc[mi][3],
                                    a0, a1, a2, a3, b0, b1);
                }
            }
            __syncthreads();
        }
        int j = jbase + n0 + 2*ql;
        float bx = b_hh[j], by = b_hh[j + 1];
        #pragma unroll
        for (int mi = 0; mi < 4; mi++) {
            int r0 = mi*16 + qid;
            *(float2*)&g_gh[(size_t)(r0    )*G3 + j] = make_float2(acc[mi][0] + bx, acc[mi][1] + by);
            *(float2*)&g_gh[(size_t)(r0 + 8)*G3 + j] = make_float2(acc[mi][2] + bx, acc[mi][3] + by);
        }
    }
}

// ============================================================
// K3b: GRU combine -> new_hidden.
// ============================================================
__global__ void k3b_gru(const float* __restrict__ hidden, float* __restrict__ out_h) {
    int gid = blockIdx.x*256 + threadIdx.x;
    int b = gid >> 9, i = gid & 511;
    const float* gx = g_gx + b*G3;
    const float* gh = g_gh + b*G3;
    float r = 1.f/(1.f + __expf(-(gx[i]        + gh[i])));
    float z = 1.f/(1.f + __expf(-(gx[Hn + i]   + gh[Hn + i])));
    float n = tanhf(gx[2*Hn + i] + r*gh[2*Hn + i]);
    float nh = (1.f - z)*n + z*hidden[b*Hn + i];
    g_act[b*KFC + i] = nh;
    if (out_h) out_h[b*Hn + i] = nh;
}

// ============================================================
// K4: prediction = act @ W_fc + b_fc via tf32 mma (R6-validated).
// ============================================================
#define K4_NT   256
#define K4_KC   32
#define K4_BP   264
#define K4_AP   36

__global__ __launch_bounds__(256, 2)
void k4_fc(const float* __restrict__ W_fc, const float* __restrict__ b_fc,
           float* __restrict__ out) {
    int lane = threadIdx.x & 31;
    int warp = threadIdx.x >> 5;
    int qid  = lane >> 2;
    int ql   = lane & 3;
    int vblk = blockIdx.x * K4_NT;
    int n0   = warp * 32;

    __shared__ uint32_t As[64 * K4_AP];
    __shared__ uint32_t Bs[K4_KC * K4_BP];

    float acc[4][4][4];
    #pragma unroll
    for (int mi = 0; mi < 4; mi++)
        #pragma unroll
        for (int ni = 0; ni < 4; ni++)
            #pragma unroll
            for (int c = 0; c < 4; c++) acc[mi][ni][c] = 0.f;

    for (int kc = 0; kc < KFC; kc += K4_KC) {
        #pragma unroll
        for (int r = 0; r < 8; r++) {
            int idx = threadIdx.x + 256*r;
            int bb = idx >> 5, kf = idx & 31;
            As[bb*K4_AP + kf] = f2tf32(g_act[bb*KFC + kc + kf]);
        }
        #pragma unroll
        for (int r = 0; r < 8; r++) {
            int idx = threadIdx.x + 256*r;
            int row = idx >> 6, c4 = (idx & 63) << 2;
            float4 w = __ldg((const float4*)&W_fc[(size_t)(kc + row)*Vn + vblk + c4]);
            uint32_t* dst = &Bs[row*K4_BP + c4];
            dst[0] = f2tf32(w.x); dst[1] = f2tf32(w.y);
            dst[2] = f2tf32(w.z); dst[3] = f2tf32(w.w);
        }
        __syncthreads();

        #pragma unroll
        for (int kk = 0; kk < K4_KC; kk += 8) {
            uint32_t af[4][4];
            #pragma unroll
            for (int mi = 0; mi < 4; mi++) {
                int m0 = mi*16 + qid;
                af[mi][0] = As[(m0    )*K4_AP + kk + ql    ];
                af[mi][1] = As[(m0 + 8)*K4_AP + kk + ql    ];
                af[mi][2] = As[(m0    )*K4_AP + kk + ql + 4];
                af[mi][3] = As[(m0 + 8)*K4_AP + kk + ql + 4];
            }
            #pragma unroll
            for (int ni = 0; ni < 4; ni++) {
                int nn = n0 + ni*8 + qid;
                uint32_t b0 = Bs[(kk + ql    )*K4_BP + nn];
                uint32_t b1 = Bs[(kk + ql + 4)*K4_BP + nn];
                #pragma unroll
                for (int mi = 0; mi < 4; mi++) {
                    mma_tf32_16x8x8(acc[mi][ni][0], acc[mi][ni][1], acc[mi][ni][2], acc[mi][ni][3],
                                    af[mi][0], af[mi][1], af[mi][2], af[mi][3], b0, b1);
                }
            }
        }
        __syncthreads();
    }

    #pragma unroll
    for (int ni = 0; ni < 4; ni++) {
        int v = vblk + n0 + ni*8 + 2*ql;
        float bx = b_fc[v], by = b_fc[v + 1];
        #pragma unroll
        for (int mi = 0; mi < 4; mi++) {
            int row0 = mi*16 + qid;
            float2 o0 = make_float2(acc[mi][ni][0] + bx, acc[mi][ni][1] + by);
            float2 o1 = make_float2(acc[mi][ni][2] + bx, acc[mi][ni][3] + by);
            *(float2*)&out[(size_t)(row0    )*Vn + v] = o0;
            *(float2*)&out[(size_t)(row0 + 8)*Vn + v] = o1;
        }
    }
}

// ============================================================
extern "C" void kernel_launch(void* const* d_in, const int* in_sizes, int n_in,
                              void* d_out, int out_size) {
    const int*   tgt    = (const int*)d_in[0];
    const float* hidden = (const float*)d_in[1];
    const float* enc    = (const float*)d_in[2];
    const int*   mask   = (const int*)d_in[3];     // bool -> int32 in harness
    const float* emb    = (const float*)d_in[4];
    const float* Wa_enc = (const float*)d_in[5];
    const float* Wa_dec = (const float*)d_in[6];
    const float* ba     = (const float*)d_in[7];
    const float* v_att  = (const float*)d_in[8];
    const float* W_ih   = (const float*)d_in[9];
    const float* W_hh   = (const float*)d_in[10];
    const float* b_ih   = (const float*)d_in[11];
    const float* b_hh   = (const float*)d_in[12];
    const float* W_fc   = (const float*)d_in[13];
    const float* b_fc   = (const float*)d_in[14];

    float* out_pred = (float*)d_out;
    float* out_h    = nullptr;
    float* out_attn = nullptr;
    if (out_size >= Bn*Vn + Bn*Hn + Bn*Sn) {
        out_h    = out_pred + (size_t)Bn*Vn;
        out_attn = out_h    + (size_t)Bn*Hn;
    }

    k0_embed_dproj<<<Bn, 256>>>(tgt, hidden, emb, Wa_dec, ba);
    k1_energy<<<dim3(2, Bn), 256>>>(enc, Wa_enc, v_att, mask);
    k2_softmax_ctx<<<Bn, 128>>>(enc, out_attn);
    k3_gates<<<24, 256>>>(hidden, W_ih, W_hh, b_ih, b_hh);
    k3b_gru<<<128, 256>>>(hidden, out_h);
    k4_fc<<<125, 256>>>(W_fc, b_fc, out_pred);
}

// round 10
// speedup vs baseline: 3.3274x; 1.5049x over previous
#include <cuda_runtime.h>
#include <math.h>
#include <stdint.h>

#define Bn   64
#define Sn   128
#define Vn   32000
#define En   256
#define EHn  512
#define Hn   512
#define An   256
#define KFC  1280   // H + Eh + E
#define G3   1536   // 3*H

// ---- scratch (allocation-free: __device__ globals) ----
__device__ float g_embedded[Bn*En];
__device__ float g_dproj[Bn*An];
__device__ float g_scores[Bn*Sn];
__device__ float g_context[Bn*EHn];
__device__ float g_gx[Bn*G3];
__device__ float g_gh[Bn*G3];
__device__ float g_act[Bn*KFC];   // row-major [b][k]: [new_hidden(512) | context(512) | embedded(256)]

__device__ __forceinline__ uint32_t f2tf32(float x) {
    uint32_t r;
    asm("cvt.rna.tf32.f32 %0, %1;" : "=r"(r) : "f"(x));
    return r;
}
__device__ __forceinline__ void mma_tf32_16x8x8(float& c0, float& c1, float& c2, float& c3,
                                                uint32_t a0, uint32_t a1, uint32_t a2, uint32_t a3,
                                                uint32_t b0, uint32_t b1) {
    asm("mma.sync.aligned.m16n8k8.row.col.f32.tf32.tf32.f32 "
        "{%0,%1,%2,%3}, {%4,%5,%6,%7}, {%8,%9}, {%0,%1,%2,%3};"
        : "+f"(c0), "+f"(c1), "+f"(c2), "+f"(c3)
        : "r"(a0), "r"(a1), "r"(a2), "r"(a3), "r"(b0), "r"(b1));
}
__device__ __forceinline__ void cp_async16(void* smem_ptr, const void* gptr) {
    uint32_t sa = (uint32_t)__cvta_generic_to_shared(smem_ptr);
    asm volatile("cp.async.cg.shared.global [%0], [%1], 16;" :: "r"(sa), "l"(gptr));
}
#define CP_COMMIT() asm volatile("cp.async.commit_group;")
#define CP_WAIT1()  asm volatile("cp.async.wait_group 1;")
#define CP_WAIT0()  asm volatile("cp.async.wait_group 0;")

// ============================================================
// K0: embedded = emb[tgt];  dproj = hidden @ Wa_dec + ba
// ============================================================
__global__ void k0_embed_dproj(const int* __restrict__ tgt,
                               const float* __restrict__ hidden,
                               const float* __restrict__ emb,
                               const float* __restrict__ Wa_dec,
                               const float* __restrict__ ba) {
    int b = blockIdx.x;
    int a = threadIdx.x;
    __shared__ float h_s[Hn];
    for (int i = threadIdx.x; i < Hn; i += 256) h_s[i] = hidden[b*Hn + i];

    int tok = tgt[b];
    float ev = emb[(size_t)tok*En + a];
    g_embedded[b*En + a] = ev;
    g_act[b*KFC + Hn + EHn + a] = ev;   // embedded at offset 1024
    __syncthreads();

    float a0 = ba[a], a1 = 0.f, a2 = 0.f, a3 = 0.f;
    #pragma unroll 4
    for (int h = 0; h < Hn; h += 4) {
        a0 += h_s[h  ] * Wa_dec[(h  )*An + a];
        a1 += h_s[h+1] * Wa_dec[(h+1)*An + a];
        a2 += h_s[h+2] * Wa_dec[(h+2)*An + a];
        a3 += h_s[h+3] * Wa_dec[(h+3)*An + a];
    }
    g_dproj[b*An + a] = (a0 + a1) + (a2 + a3);
}

// ============================================================
// K1: energy = tanh(enc@Wa_enc + dproj);  scores = energy . v_att  [tf32 MMA]
// grid (2 s-halves, 64 b), 256 thr.  (R9-validated)
// ============================================================
#define K1_KC 32
#define K1_AP 36
#define K1_BP 264

__global__ __launch_bounds__(256, 1)
void k1_energy(const float* __restrict__ enc,
               const float* __restrict__ Wa_enc,
               const float* __restrict__ v_att,
               const int* __restrict__ mask) {
    int b  = blockIdx.y;
    int s0 = blockIdx.x * 64;
    int lane = threadIdx.x & 31;
    int warp = threadIdx.x >> 5;
    int qid = lane >> 2, ql = lane & 3;
    int n0 = warp * 32;

    __shared__ uint32_t As[64 * K1_AP];
    __shared__ uint32_t Bs[K1_KC * K1_BP];
    __shared__ float red[64][8];

    float acc[4][4][4];
    #pragma unroll
    for (int mi = 0; mi < 4; mi++)
        #pragma unroll
        for (int ni = 0; ni < 4; ni++)
            #pragma unroll
            for (int c = 0; c < 4; c++) acc[mi][ni][c] = 0.f;

    for (int kc = 0; kc < EHn; kc += K1_KC) {
        #pragma unroll
        for (int r = 0; r < 8; r++) {
            int idx = threadIdx.x + 256*r;
            int m = idx >> 5, kf = idx & 31;
            As[m*K1_AP + kf] = f2tf32(enc[((size_t)(b*Sn + s0 + m))*EHn + kc + kf]);
        }
        #pragma unroll
        for (int r = 0; r < 8; r++) {
            int idx = threadIdx.x + 256*r;
            int row = idx >> 6, c4 = (idx & 63) << 2;
            float4 w = __ldg((const float4*)&Wa_enc[(size_t)(kc + row)*An + c4]);
            uint32_t* dst = &Bs[row*K1_BP + c4];
            dst[0] = f2tf32(w.x); dst[1] = f2tf32(w.y);
            dst[2] = f2tf32(w.z); dst[3] = f2tf32(w.w);
        }
        __syncthreads();

        #pragma unroll
        for (int kk = 0; kk < K1_KC; kk += 8) {
            uint32_t af[4][4];
            #pragma unroll
            for (int mi = 0; mi < 4; mi++) {
                int m0 = mi*16 + qid;
                af[mi][0] = As[(m0    )*K1_AP + kk + ql    ];
                af[mi][1] = As[(m0 + 8)*K1_AP + kk + ql    ];
                af[mi][2] = As[(m0    )*K1_AP + kk + ql + 4];
                af[mi][3] = As[(m0 + 8)*K1_AP + kk + ql + 4];
            }
            #pragma unroll
            for (int ni = 0; ni < 4; ni++) {
                int nn = n0 + ni*8 + qid;
                uint32_t b0 = Bs[(kk + ql    )*K1_BP + nn];
                uint32_t b1 = Bs[(kk + ql + 4)*K1_BP + nn];
                #pragma unroll
                for (int mi = 0; mi < 4; mi++)
                    mma_tf32_16x8x8(acc[mi][ni][0], acc[mi][ni][1], acc[mi][ni][2], acc[mi][ni][3],
                                    af[mi][0], af[mi][1], af[mi][2], af[mi][3], b0, b1);
            }
        }
        __syncthreads();
    }

    float part[4][2] = {};
    #pragma unroll
    for (int ni = 0; ni < 4; ni++) {
        int col = n0 + ni*8 + 2*ql;
        float2 dp = *(const float2*)&g_dproj[b*An + col];
        float2 va = *(const float2*)&v_att[col];
        #pragma unroll
        for (int mi = 0; mi < 4; mi++) {
            part[mi][0] += tanhf(acc[mi][ni][0] + dp.x)*va.x + tanhf(acc[mi][ni][1] + dp.y)*va.y;
            part[mi][1] += tanhf(acc[mi][ni][2] + dp.x)*va.x + tanhf(acc[mi][ni][3] + dp.y)*va.y;
        }
    }
    #pragma unroll
    for (int mi = 0; mi < 4; mi++) {
        #pragma unroll
        for (int h = 0; h < 2; h++) {
            float p = part[mi][h];
            p += __shfl_xor_sync(0xffffffffu, p, 1);
            p += __shfl_xor_sync(0xffffffffu, p, 2);
            if (ql == 0) red[mi*16 + h*8 + qid][warp] = p;
        }
    }
    __syncthreads();
    if (threadIdx.x < 64) {
        int row = threadIdx.x;
        float s = 0.f;
        #pragma unroll
        for (int w = 0; w < 8; w++) s += red[row][w];
        int sg = s0 + row;
        g_scores[b*Sn + sg] = mask[b*Sn + sg] ? s : -1e9f;
    }
}

// ============================================================
// K2: softmax over S, context = attn @ enc.  grid 64 (b), 128 threads.
// ============================================================
__global__ void k2_softmax_ctx(const float* __restrict__ enc,
                               float* __restrict__ out_attn) {
    int b = blockIdx.x;
    int t = threadIdx.x;
    __shared__ float at_s[Sn];
    __shared__ float red[4];

    float v = g_scores[b*Sn + t];
    float m = v;
    #pragma unroll
    for (int o = 16; o > 0; o >>= 1) m = fmaxf(m, __shfl_xor_sync(0xffffffffu, m, o));
    if ((t & 31) == 0) red[t >> 5] = m;
    __syncthreads();
    m = fmaxf(fmaxf(red[0], red[1]), fmaxf(red[2], red[3]));
    __syncthreads();

    float ex = __expf(v - m);
    float sm = ex;
    #pragma unroll
    for (int o = 16; o > 0; o >>= 1) sm += __shfl_xor_sync(0xffffffffu, sm, o);
    if ((t & 31) == 0) red[t >> 5] = sm;
    __syncthreads();
    float tot = red[0] + red[1] + red[2] + red[3];

    float at = ex / tot;
    at_s[t] = at;
    if (out_attn) out_attn[b*Sn + t] = at;
    __syncthreads();

    for (int h = t; h < EHn; h += 128) {
        float c = 0.f;
        #pragma unroll 8
        for (int s = 0; s < Sn; s++) c += at_s[s] * enc[((size_t)(b*Sn + s))*EHn + h];
        g_context[b*EHn + h] = c;
        g_act[b*KFC + Hn + h] = c;
    }
}

// ============================================================
// K3: gate GEMMs, tf32 MMA + cp.async double-buffer.
// grid (24 j-tiles of 64, 2 phases).  phase 0: gx (K=768), phase 1: gh (K=512).
// A and B both double-buffered raw fp32 in smem; cvt at fragment load.
// ============================================================
#define K3_P 36

__global__ __launch_bounds__(256, 2)
void k3_gates(const float* __restrict__ hidden,
              const float* __restrict__ W_ih, const float* __restrict__ W_hh,
              const float* __restrict__ b_ih, const float* __restrict__ b_hh) {
    int lane = threadIdx.x & 31;
    int warp = threadIdx.x >> 5;
    int qid = lane >> 2, ql = lane & 3;
    int jbase = blockIdx.x * 64;
    int phase = blockIdx.y;
    int n0 = warp * 8;

    const float* W   = phase ? W_hh : W_ih;
    const float* bia = phase ? b_hh : b_ih;
    float*       gout = phase ? g_gh : g_gx;
    int Kt  = phase ? 512 : 768;
    int NCH = Kt >> 5;

    __shared__ float As[2][64 * K3_P];
    __shared__ float Bs[2][64 * K3_P];

    // fill helpers (2 cp.async.16 each per thread)
    auto fillA = [&](int c, int buf) {
        int kc = c << 5;
        #pragma unroll
        for (int r = 0; r < 2; r++) {
            int idx = threadIdx.x + 256*r;           // 512 quads
            int m = idx >> 3, k4 = (idx & 7) << 2;
            const float* src;
            if (phase) {
                src = &hidden[m*Hn + kc + k4];
            } else {
                int kk = kc + k4;
                src = (kk < En) ? &g_embedded[m*En + kk]
                                : &g_context[m*EHn + (kk - En)];
            }
            cp_async16(&As[buf][m*K3_P + k4], src);
        }
    };
    auto fillB = [&](int c, int buf) {
        int kc = c << 5;
        #pragma unroll
        for (int r = 0; r < 2; r++) {
            int idx = threadIdx.x + 256*r;
            int j = idx >> 3, k4 = (idx & 7) << 2;
            cp_async16(&Bs[buf][j*K3_P + k4], &W[(size_t)(jbase + j)*Kt + kc + k4]);
        }
    };

    float acc[4][4];
    #pragma unroll
    for (int mi = 0; mi < 4; mi++)
        #pragma unroll
        for (int c = 0; c < 4; c++) acc[mi][c] = 0.f;

    fillA(0, 0); fillB(0, 0); CP_COMMIT();

    for (int c = 0; c < NCH; c++) {
        int buf = c & 1;
        if (c + 1 < NCH) {
            fillA(c + 1, buf ^ 1); fillB(c + 1, buf ^ 1); CP_COMMIT();
            CP_WAIT1();
        } else {
            CP_WAIT0();
        }
        __syncthreads();

        #pragma unroll
        for (int kk = 0; kk < 32; kk += 8) {
            int nn = n0 + qid;
            uint32_t b0 = f2tf32(Bs[buf][nn*K3_P + kk + ql    ]);
            uint32_t b1 = f2tf32(Bs[buf][nn*K3_P + kk + ql + 4]);
            #pragma unroll
            for (int mi = 0; mi < 4; mi++) {
                int m0 = mi*16 + qid;
                uint32_t a0 = f2tf32(As[buf][(m0    )*K3_P + kk + ql    ]);
                uint32_t a1 = f2tf32(As[buf][(m0 + 8)*K3_P + kk + ql    ]);
                uint32_t a2 = f2tf32(As[buf][(m0    )*K3_P + kk + ql + 4]);
                uint32_t a3 = f2tf32(As[buf][(m0 + 8)*K3_P + kk + ql + 4]);
                mma_tf32_16x8x8(acc[mi][0], acc[mi][1], acc[mi][2], acc[mi][3],
                                a0, a1, a2, a3, b0, b1);
            }
        }
        __syncthreads();
    }

    int j = jbase + n0 + 2*ql;
    float bx = bia[j], by = bia[j + 1];
    #pragma unroll
    for (int mi = 0; mi < 4; mi++) {
        int r0 = mi*16 + qid;
        *(float2*)&gout[(size_t)(r0    )*G3 + j] = make_float2(acc[mi][0] + bx, acc[mi][1] + by);
        *(float2*)&gout[(size_t)(r0 + 8)*G3 + j] = make_float2(acc[mi][2] + bx, acc[mi][3] + by);
    }
}

// ============================================================
// K3b: GRU combine -> new_hidden.
// ============================================================
__global__ void k3b_gru(const float* __restrict__ hidden, float* __restrict__ out_h) {
    int gid = blockIdx.x*256 + threadIdx.x;
    int b = gid >> 9, i = gid & 511;
    const float* gx = g_gx + b*G3;
    const float* gh = g_gh + b*G3;
    float r = 1.f/(1.f + __expf(-(gx[i]        + gh[i])));
    float z = 1.f/(1.f + __expf(-(gx[Hn + i]   + gh[Hn + i])));
    float n = tanhf(gx[2*Hn + i] + r*gh[2*Hn + i]);
    float nh = (1.f - z)*n + z*hidden[b*Hn + i];
    g_act[b*KFC + i] = nh;
    if (out_h) out_h[b*Hn + i] = nh;
}

// ============================================================
// K4: prediction = act @ W_fc + b_fc via tf32 mma + cp.async pipeline.
// grid 250 (v-tiles of 128), 256 thr (8 warps, n16 each).
// B double-buffered cp.async; A single-buffer with register staging.
// ============================================================
#define K4_NT   128
#define K4_AP   36
#define K4_BP   136
#define K4_NCH  40    // KFC/32

__global__ __launch_bounds__(256, 2)
void k4_fc(const float* __restrict__ W_fc, const float* __restrict__ b_fc,
           float* __restrict__ out) {
    int lane = threadIdx.x & 31;
    int warp = threadIdx.x >> 5;
    int qid  = lane >> 2;
    int ql   = lane & 3;
    int vblk = blockIdx.x * K4_NT;
    int n0   = warp * 16;

    __shared__ float As[64 * K4_AP];          //  9216 B (raw fp32)
    __shared__ float Bs[2][32 * K4_BP];       // 34816 B (raw fp32)

    int am = threadIdx.x >> 5;                // A-fill row base: idx = tid+256r -> m
    int akf = threadIdx.x & 31;

    auto fillB = [&](int c, int buf) {
        int kc = c << 5;
        #pragma unroll
        for (int r = 0; r < 4; r++) {
            int idx = threadIdx.x + 256*r;        // 1024 quads
            int row = idx >> 5, c4 = (idx & 31) << 2;
            cp_async16(&Bs[buf][row*K4_BP + c4],
                       &W_fc[(size_t)(kc + row)*Vn + vblk + c4]);
        }
    };

    float acc[4][2][4];
    #pragma unroll
    for (int mi = 0; mi < 4; mi++)
        #pragma unroll
        for (int ni = 0; ni < 2; ni++)
            #pragma unroll
            for (int c = 0; c < 4; c++) acc[mi][ni][c] = 0.f;

    // preload: B chunk 0 async, A chunk 0 sync
    fillB(0, 0); CP_COMMIT();
    #pragma unroll
    for (int r = 0; r < 8; r++) {
        int m = am + 8*r;
        As[m*K4_AP + akf] = g_act[m*KFC + akf];
    }

    for (int c = 0; c < K4_NCH; c++) {
        int buf = c & 1;
        float ar[8];
        bool hasNext = (c + 1 < K4_NCH);
        if (hasNext) {
            int kc1 = (c + 1) << 5;
            #pragma unroll
            for (int r = 0; r < 8; r++) {
                int m = am + 8*r;
                ar[r] = g_act[m*KFC + kc1 + akf];   // early LDG, staged in regs
            }
            fillB(c + 1, buf ^ 1); CP_COMMIT();
            CP_WAIT1();
        } else {
            CP_WAIT0();
        }
        __syncthreads();

        #pragma unroll
        for (int kk = 0; kk < 32; kk += 8) {
            uint32_t af[4][4];
            #pragma unroll
            for (int mi = 0; mi < 4; mi++) {
                int m0 = mi*16 + qid;
                af[mi][0] = f2tf32(As[(m0    )*K4_AP + kk + ql    ]);
                af[mi][1] = f2tf32(As[(m0 + 8)*K4_AP + kk + ql    ]);
                af[mi][2] = f2tf32(As[(m0    )*K4_AP + kk + ql + 4]);
                af[mi][3] = f2tf32(As[(m0 + 8)*K4_AP + kk + ql + 4]);
            }
            #pragma unroll
            for (int ni = 0; ni < 2; ni++) {
                int nn = n0 + ni*8 + qid;
                uint32_t b0 = f2tf32(Bs[buf][(kk + ql    )*K4_BP + nn]);
                uint32_t b1 = f2tf32(Bs[buf][(kk + ql + 4)*K4_BP + nn]);
                #pragma unroll
                for (int mi = 0; mi < 4; mi++) {
                    mma_tf32_16x8x8(acc[mi][ni][0], acc[mi][ni][1], acc[mi][ni][2], acc[mi][ni][3],
                                    af[mi][0], af[mi][1], af[mi][2], af[mi][3], b0, b1);
                }
            }
        }
        __syncthreads();

        if (hasNext) {
            #pragma unroll
            for (int r = 0; r < 8; r++) {
                int m = am + 8*r;
                As[m*K4_AP + akf] = ar[r];          // visible after next iter's sync
            }
        }
    }

    #pragma unroll
    for (int ni = 0; ni < 2; ni++) {
        int v = vblk + n0 + ni*8 + 2*ql;
        float bx = b_fc[v], by = b_fc[v + 1];
        #pragma unroll
        for (int mi = 0; mi < 4; mi++) {
            int row0 = mi*16 + qid;
            float2 o0 = make_float2(acc[mi][ni][0] + bx, acc[mi][ni][1] + by);
            float2 o1 = make_float2(acc[mi][ni][2] + bx, acc[mi][ni][3] + by);
            *(float2*)&out[(size_t)(row0    )*Vn + v] = o0;
            *(float2*)&out[(size_t)(row0 + 8)*Vn + v] = o1;
        }
    }
}

// ============================================================
extern "C" void kernel_launch(void* const* d_in, const int* in_sizes, int n_in,
                              void* d_out, int out_size) {
    const int*   tgt    = (const int*)d_in[0];
    const float* hidden = (const float*)d_in[1];
    const float* enc    = (const float*)d_in[2];
    const int*   mask   = (const int*)d_in[3];     // bool -> int32 in harness
    const float* emb    = (const float*)d_in[4];
    const float* Wa_enc = (const float*)d_in[5];
    const float* Wa_dec = (const float*)d_in[6];
    const float* ba     = (const float*)d_in[7];
    const float* v_att  = (const float*)d_in[8];
    const float* W_ih   = (const float*)d_in[9];
    const float* W_hh   = (const float*)d_in[10];
    const float* b_ih   = (const float*)d_in[11];
    const float* b_hh   = (const float*)d_in[12];
    const float* W_fc   = (const float*)d_in[13];
    const float* b_fc   = (const float*)d_in[14];

    float* out_pred = (float*)d_out;
    float* out_h    = nullptr;
    float* out_attn = nullptr;
    if (out_size >= Bn*Vn + Bn*Hn + Bn*Sn) {
        out_h    = out_pred + (size_t)Bn*Vn;
        out_attn = out_h    + (size_t)Bn*Hn;
    }

    k0_embed_dproj<<<Bn, 256>>>(tgt, hidden, emb, Wa_dec, ba);
    k1_energy<<<dim3(2, Bn), 256>>>(enc, Wa_enc, v_att, mask);
    k2_softmax_ctx<<<Bn, 128>>>(enc, out_attn);
    k3_gates<<<dim3(24, 2), 256>>>(hidden, W_ih, W_hh, b_ih, b_hh);
    k3b_gru<<<128, 256>>>(hidden, out_h);
    k4_fc<<<250, 256>>>(W_fc, b_fc, out_pred);
}

// round 12
// speedup vs baseline: 3.7304x; 1.1211x over previous
#include <cuda_runtime.h>
#include <math.h>
#include <stdint.h>

#define Bn   64
#define Sn   128
#define Vn   32000
#define En   256
#define EHn  512
#define Hn   512
#define An   256
#define KFC  1280   // H + Eh + E
#define G3   1536   // 3*H

// ---- scratch (allocation-free: __device__ globals) ----
__device__ float g_embedded[Bn*En];
__device__ float g_dproj[Bn*An];
__device__ float g_scores[Bn*Sn];
__device__ float g_context[Bn*EHn];
__device__ float g_gx[Bn*G3];
__device__ float g_gh[Bn*G3];
__device__ float g_act[Bn*KFC];   // row-major [b][k]

__device__ __forceinline__ uint32_t f2tf32(float x) {
    uint32_t r;
    asm("cvt.rna.tf32.f32 %0, %1;" : "=r"(r) : "f"(x));
    return r;
}
__device__ __forceinline__ void mma_tf32_16x8x8(float& c0, float& c1, float& c2, float& c3,
                                                uint32_t a0, uint32_t a1, uint32_t a2, uint32_t a3,
                                                uint32_t b0, uint32_t b1) {
    asm("mma.sync.aligned.m16n8k8.row.col.f32.tf32.tf32.f32 "
        "{%0,%1,%2,%3}, {%4,%5,%6,%7}, {%8,%9}, {%0,%1,%2,%3};"
        : "+f"(c0), "+f"(c1), "+f"(c2), "+f"(c3)
        : "r"(a0), "r"(a1), "r"(a2), "r"(a3), "r"(b0), "r"(b1));
}
__device__ __forceinline__ void cp_async16(void* smem_ptr, const void* gptr) {
    uint32_t sa = (uint32_t)__cvta_generic_to_shared(smem_ptr);
    asm volatile("cp.async.cg.shared.global [%0], [%1], 16;" :: "r"(sa), "l"(gptr));
}
#define CP_COMMIT() asm volatile("cp.async.commit_group;")
#define CP_WAIT3()  asm volatile("cp.async.wait_group 3;")
#define CP_WAIT1()  asm volatile("cp.async.wait_group 1;")
#define CP_WAIT0()  asm volatile("cp.async.wait_group 0;")

// ============================================================
// K0: embedded = emb[tgt];  dproj = hidden @ Wa_dec + ba
// ============================================================
__global__ void k0_embed_dproj(const int* __restrict__ tgt,
                               const float* __restrict__ hidden,
                               const float* __restrict__ emb,
                               const float* __restrict__ Wa_dec,
                               const float* __restrict__ ba) {
    int b = blockIdx.x;
    int a = threadIdx.x;
    __shared__ float h_s[Hn];
    for (int i = threadIdx.x; i < Hn; i += 256) h_s[i] = hidden[b*Hn + i];

    int tok = tgt[b];
    float ev = emb[(size_t)tok*En + a];
    g_embedded[b*En + a] = ev;
    g_act[b*KFC + Hn + EHn + a] = ev;
    __syncthreads();

    float a0 = ba[a], a1 = 0.f, a2 = 0.f, a3 = 0.f;
    #pragma unroll 4
    for (int h = 0; h < Hn; h += 4) {
        a0 += h_s[h  ] * Wa_dec[(h  )*An + a];
        a1 += h_s[h+1] * Wa_dec[(h+1)*An + a];
        a2 += h_s[h+2] * Wa_dec[(h+2)*An + a];
        a3 += h_s[h+3] * Wa_dec[(h+3)*An + a];
    }
    g_dproj[b*An + a] = (a0 + a1) + (a2 + a3);
}

// ============================================================
// K1: energy GEMM, tf32 MMA + cp.async double buffer (KC=16).
// grid (2 s-halves, 64 b), 256 thr.  M=64, N=256, K=512, NCH=32.
// ============================================================
#define K1_KC 16
#define K1_AP 20
#define K1_BP 264
#define K1_NCH 32

__global__ __launch_bounds__(256, 1)
void k1_energy(const float* __restrict__ enc,
               const float* __restrict__ Wa_enc,
               const float* __restrict__ v_att,
               const int* __restrict__ mask) {
    int b  = blockIdx.y;
    int s0 = blockIdx.x * 64;
    int lane = threadIdx.x & 31;
    int warp = threadIdx.x >> 5;
    int qid = lane >> 2, ql = lane & 3;
    int n0 = warp * 32;

    __shared__ float As[2][64 * K1_AP];
    __shared__ float Bs[2][K1_KC * K1_BP];
    __shared__ float red[64][8];

    auto fillA = [&](int c, int buf) {
        int kc = c << 4;
        int m = threadIdx.x >> 2, k4 = (threadIdx.x & 3) << 2;  // 256 quads
        cp_async16(&As[buf][m*K1_AP + k4],
                   &enc[((size_t)(b*Sn + s0 + m))*EHn + kc + k4]);
    };
    auto fillB = [&](int c, int buf) {
        int kc = c << 4;
        #pragma unroll
        for (int r = 0; r < 4; r++) {
            int idx = threadIdx.x + 256*r;                       // 1024 quads
            int row = idx >> 6, c4 = (idx & 63) << 2;
            cp_async16(&Bs[buf][row*K1_BP + c4], &Wa_enc[(size_t)(kc + row)*An + c4]);
        }
    };

    float acc[4][4][4];
    #pragma unroll
    for (int mi = 0; mi < 4; mi++)
        #pragma unroll
        for (int ni = 0; ni < 4; ni++)
            #pragma unroll
            for (int c = 0; c < 4; c++) acc[mi][ni][c] = 0.f;

    fillA(0, 0); fillB(0, 0); CP_COMMIT();

    for (int c = 0; c < K1_NCH; c++) {
        int buf = c & 1;
        if (c + 1 < K1_NCH) {
            fillA(c + 1, buf ^ 1); fillB(c + 1, buf ^ 1); CP_COMMIT();
            CP_WAIT1();
        } else {
            CP_WAIT0();
        }
        __syncthreads();

        #pragma unroll
        for (int kk = 0; kk < K1_KC; kk += 8) {
            uint32_t af[4][4];
            #pragma unroll
            for (int mi = 0; mi < 4; mi++) {
                int m0 = mi*16 + qid;
                af[mi][0] = f2tf32(As[buf][(m0    )*K1_AP + kk + ql    ]);
                af[mi][1] = f2tf32(As[buf][(m0 + 8)*K1_AP + kk + ql    ]);
                af[mi][2] = f2tf32(As[buf][(m0    )*K1_AP + kk + ql + 4]);
                af[mi][3] = f2tf32(As[buf][(m0 + 8)*K1_AP + kk + ql + 4]);
            }
            #pragma unroll
            for (int ni = 0; ni < 4; ni++) {
                int nn = n0 + ni*8 + qid;
                uint32_t b0 = f2tf32(Bs[buf][(kk + ql    )*K1_BP + nn]);
                uint32_t b1 = f2tf32(Bs[buf][(kk + ql + 4)*K1_BP + nn]);
                #pragma unroll
                for (int mi = 0; mi < 4; mi++)
                    mma_tf32_16x8x8(acc[mi][ni][0], acc[mi][ni][1], acc[mi][ni][2], acc[mi][ni][3],
                                    af[mi][0], af[mi][1], af[mi][2], af[mi][3], b0, b1);
            }
        }
        __syncthreads();
    }

    float part[4][2] = {};
    #pragma unroll
    for (int ni = 0; ni < 4; ni++) {
        int col = n0 + ni*8 + 2*ql;
        float2 dp = *(const float2*)&g_dproj[b*An + col];
        float2 va = *(const float2*)&v_att[col];
        #pragma unroll
        for (int mi = 0; mi < 4; mi++) {
            part[mi][0] += tanhf(acc[mi][ni][0] + dp.x)*va.x + tanhf(acc[mi][ni][1] + dp.y)*va.y;
            part[mi][1] += tanhf(acc[mi][ni][2] + dp.x)*va.x + tanhf(acc[mi][ni][3] + dp.y)*va.y;
        }
    }
    #pragma unroll
    for (int mi = 0; mi < 4; mi++) {
        #pragma unroll
        for (int h = 0; h < 2; h++) {
            float p = part[mi][h];
            p += __shfl_xor_sync(0xffffffffu, p, 1);
            p += __shfl_xor_sync(0xffffffffu, p, 2);
            if (ql == 0) red[mi*16 + h*8 + qid][warp] = p;
        }
    }
    __syncthreads();
    if (threadIdx.x < 64) {
        int row = threadIdx.x;
        float s = 0.f;
        #pragma unroll
        for (int w = 0; w < 8; w++) s += red[row][w];
        int sg = s0 + row;
        g_scores[b*Sn + sg] = mask[b*Sn + sg] ? s : -1e9f;
    }
}

// ============================================================
// K2: softmax + context.  grid (64 b, 2 h-halves), 128 threads.
// ============================================================
__global__ void k2_softmax_ctx(const float* __restrict__ enc,
                               float* __restrict__ out_attn) {
    int b = blockIdx.x;
    int t = threadIdx.x;
    __shared__ float at_s[Sn];
    __shared__ float red[4];

    float v = g_scores[b*Sn + t];
    float m = v;
    #pragma unroll
    for (int o = 16; o > 0; o >>= 1) m = fmaxf(m, __shfl_xor_sync(0xffffffffu, m, o));
    if ((t & 31) == 0) red[t >> 5] = m;
    __syncthreads();
    m = fmaxf(fmaxf(red[0], red[1]), fmaxf(red[2], red[3]));
    __syncthreads();

    float ex = __expf(v - m);
    float sm = ex;
    #pragma unroll
    for (int o = 16; o > 0; o >>= 1) sm += __shfl_xor_sync(0xffffffffu, sm, o);
    if ((t & 31) == 0) red[t >> 5] = sm;
    __syncthreads();
    float tot = red[0] + red[1] + red[2] + red[3];

    float at = ex / tot;
    at_s[t] = at;
    if (blockIdx.y == 0 && out_attn) out_attn[b*Sn + t] = at;
    __syncthreads();

    int h0 = blockIdx.y * 256;
    for (int h = h0 + t; h < h0 + 256; h += 128) {
        float c = 0.f;
        #pragma unroll 8
        for (int s = 0; s < Sn; s++) c += at_s[s] * enc[((size_t)(b*Sn + s))*EHn + h];
        g_context[b*EHn + h] = c;
        g_act[b*KFC + Hn + h] = c;
    }
}

// ============================================================
// K3: gate GEMMs, tf32 MMA + cp.async double buffer.
// grid (48 j-tiles of 32, 2 phases), 256 thr.
// warps 0-3: rows 0-31, warps 4-7: rows 32-63.
// ============================================================
#define K3_P 36

__global__ __launch_bounds__(256, 2)
void k3_gates(const float* __restrict__ hidden,
              const float* __restrict__ W_ih, const float* __restrict__ W_hh,
              const float* __restrict__ b_ih, const float* __restrict__ b_hh) {
    int lane = threadIdx.x & 31;
    int warp = threadIdx.x >> 5;
    int qid = lane >> 2, ql = lane & 3;
    int jbase = blockIdx.x * 32;
    int phase = blockIdx.y;
    int n0 = (warp & 3) * 8;
    int mbase = (warp >> 2) * 32;

    const float* W    = phase ? W_hh : W_ih;
    const float* bia  = phase ? b_hh : b_ih;
    float*       gout = phase ? g_gh : g_gx;
    int Kt  = phase ? 512 : 768;
    int NCH = Kt >> 5;

    __shared__ float As[2][64 * K3_P];
    __shared__ float Bs[2][32 * K3_P];

    auto fillA = [&](int c, int buf) {
        int kc = c << 5;
        #pragma unroll
        for (int r = 0; r < 2; r++) {
            int idx = threadIdx.x + 256*r;               // 512 quads
            int m = idx >> 3, k4 = (idx & 7) << 2;
            const float* src;
            if (phase) {
                src = &hidden[m*Hn + kc + k4];
            } else {
                int kk = kc + k4;
                src = (kk < En) ? &g_embedded[m*En + kk]
                                : &g_context[m*EHn + (kk - En)];
            }
            cp_async16(&As[buf][m*K3_P + k4], src);
        }
    };
    auto fillB = [&](int c, int buf) {
        int kc = c << 5;
        int j = threadIdx.x >> 3, k4 = (threadIdx.x & 7) << 2;   // 256 quads
        cp_async16(&Bs[buf][j*K3_P + k4], &W[(size_t)(jbase + j)*Kt + kc + k4]);
    };

    float acc[2][4];
    #pragma unroll
    for (int mi = 0; mi < 2; mi++)
        #pragma unroll
        for (int c = 0; c < 4; c++) acc[mi][c] = 0.f;

    fillA(0, 0); fillB(0, 0); CP_COMMIT();

    for (int c = 0; c < NCH; c++) {
        int buf = c & 1;
        if (c + 1 < NCH) {
            fillA(c + 1, buf ^ 1); fillB(c + 1, buf ^ 1); CP_COMMIT();
            CP_WAIT1();
        } else {
            CP_WAIT0();
        }
        __syncthreads();

        #pragma unroll
        for (int kk = 0; kk < 32; kk += 8) {
            int nn = n0 + qid;
            uint32_t b0 = f2tf32(Bs[buf][nn*K3_P + kk + ql    ]);
            uint32_t b1 = f2tf32(Bs[buf][nn*K3_P + kk + ql + 4]);
            #pragma unroll
            for (int mi = 0; mi < 2; mi++) {
                int m0 = mbase + mi*16 + qid;
                uint32_t a0 = f2tf32(As[buf][(m0    )*K3_P + kk + ql    ]);
                uint32_t a1 = f2tf32(As[buf][(m0 + 8)*K3_P + kk + ql    ]);
                uint32_t a2 = f2tf32(As[buf][(m0    )*K3_P + kk + ql + 4]);
                uint32_t a3 = f2tf32(As[buf][(m0 + 8)*K3_P + kk + ql + 4]);
                mma_tf32_16x8x8(acc[mi][0], acc[mi][1], acc[mi][2], acc[mi][3],
                                a0, a1, a2, a3, b0, b1);
            }
        }
        __syncthreads();
    }

    int j = jbase + n0 + 2*ql;
    float bx = bia[j], by = bia[j + 1];
    #pragma unroll
    for (int mi = 0; mi < 2; mi++) {
        int r0 = mbase + mi*16 + qid;
        *(float2*)&gout[(size_t)(r0    )*G3 + j] = make_float2(acc[mi][0] + bx, acc[mi][1] + by);
        *(float2*)&gout[(size_t)(r0 + 8)*G3 + j] = make_float2(acc[mi][2] + bx, acc[mi][3] + by);
    }
}

// ============================================================
// K3b: GRU combine -> new_hidden.
// ============================================================
__global__ void k3b_gru(const float* __restrict__ hidden, float* __restrict__ out_h) {
    int gid = blockIdx.x*256 + threadIdx.x;
    int b = gid >> 9, i = gid & 511;
    const float* gx = g_gx + b*G3;
    const float* gh = g_gh + b*G3;
    float r = 1.f/(1.f + __expf(-(gx[i]        + gh[i])));
    float z = 1.f/(1.f + __expf(-(gx[Hn + i]   + gh[Hn + i])));
    float n = tanhf(gx[2*Hn + i] + r*gh[2*Hn + i]);
    float nh = (1.f - z)*n + z*hidden[b*Hn + i];
    g_act[b*KFC + i] = nh;
    if (out_h) out_h[b*Hn + i] = nh;
}

// ============================================================
// K4: FC GEMM, tf32 MMA + 4-stage cp.async pipeline (KC=16).
// grid 250 (v-tiles of 128), 256 thr (8 warps, n16 each).
// ============================================================
#define K4_NT   128
#define K4_KC   16
#define K4_AP   20
#define K4_BP   136
#define K4_NCH  80    // KFC/16

__global__ __launch_bounds__(256, 2)
void k4_fc(const float* __restrict__ W_fc, const float* __restrict__ b_fc,
           float* __restrict__ out) {
    int lane = threadIdx.x & 31;
    int warp = threadIdx.x >> 5;
    int qid  = lane >> 2;
    int ql   = lane & 3;
    int vblk = blockIdx.x * K4_NT;
    int n0   = warp * 16;

    __shared__ float As[64 * K4_AP];          //  5120 B
    __shared__ float Bs[4][K4_KC * K4_BP];    // 34816 B

    int amb = threadIdx.x >> 4;               // 0..15
    int akf = threadIdx.x & 15;               // 0..15

    auto fillB = [&](int c) {
        int buf = c & 3;
        int kc = c << 4;
        #pragma unroll
        for (int r = 0; r < 2; r++) {
            int idx = threadIdx.x + 256*r;        // 512 quads
            int row = idx >> 5, c4 = (idx & 31) << 2;
            cp_async16(&Bs[buf][row*K4_BP + c4],
                       &W_fc[(size_t)(kc + row)*Vn + vblk + c4]);
        }
    };

    float acc[4][2][4];
    #pragma unroll
    for (int mi = 0; mi < 4; mi++)
        #pragma unroll
        for (int ni = 0; ni < 2; ni++)
            #pragma unroll
            for (int c = 0; c < 4; c++) acc[mi][ni][c] = 0.f;

    fillB(0); CP_COMMIT();
    fillB(1); CP_COMMIT();
    fillB(2); CP_COMMIT();
    #pragma unroll
    for (int r = 0; r < 4; r++) {
        int m = amb + 16*r;
        As[m*K4_AP + akf] = g_act[m*KFC + akf];
    }

    for (int c = 0; c < K4_NCH; c++) {
        int buf = c & 3;
        float ar[4];
        bool hasNext = (c + 1 < K4_NCH);
        if (hasNext) {
            int kc1 = (c + 1) << 4;
            #pragma unroll
            for (int r = 0; r < 4; r++) {
                int m = amb + 16*r;
                ar[r] = g_act[m*KFC + kc1 + akf];
            }
        }
        if (c + 3 < K4_NCH) {
            fillB(c + 3); CP_COMMIT();
            CP_WAIT3();
        } else {
            CP_WAIT0();
        }
        __syncthreads();

        #pragma unroll
        for (int kk = 0; kk < K4_KC; kk += 8) {
            uint32_t af[4][4];
            #pragma unroll
            for (int mi = 0; mi < 4; mi++) {
                int m0 = mi*16 + qid;
                af[mi][0] = f2tf32(As[(m0    )*K4_AP + kk + ql    ]);
                af[mi][1] = f2tf32(As[(m0 + 8)*K4_AP + kk + ql    ]);
                af[mi][2] = f2tf32(As[(m0    )*K4_AP + kk + ql + 4]);
                af[mi][3] = f2tf32(As[(m0 + 8)*K4_AP + kk + ql + 4]);
            }
            #pragma unroll
            for (int ni = 0; ni < 2; ni++) {
                int nn = n0 + ni*8 + qid;
                uint32_t b0 = f2tf32(Bs[buf][(kk + ql    )*K4_BP + nn]);
                uint32_t b1 = f2tf32(Bs[buf][(kk + ql + 4)*K4_BP + nn]);
                #pragma unroll
                for (int mi = 0; mi < 4; mi++) {
                    mma_tf32_16x8x8(acc[mi][ni][0], acc[mi][ni][1], acc[mi][ni][2], acc[mi][ni][3],
                                    af[mi][0], af[mi][1], af[mi][2], af[mi][3], b0, b1);
                }
            }
        }
        __syncthreads();

        if (hasNext) {
            #pragma unroll
            for (int r = 0; r < 4; r++) {
                int m = amb + 16*r;
                As[m*K4_AP + akf] = ar[r];
            }
        }
    }

    #pragma unroll
    for (int ni = 0; ni < 2; ni++) {
        int v = vblk + n0 + ni*8 + 2*ql;
        float bx = b_fc[v], by = b_fc[v + 1];
        #pragma unroll
        for (int mi = 0; mi < 4; mi++) {
            int row0 = mi*16 + qid;
            float2 o0 = make_float2(acc[mi][ni][0] + bx, acc[mi][ni][1] + by);
            float2 o1 = make_float2(acc[mi][ni][2] + bx, acc[mi][ni][3] + by);
            *(float2*)&out[(size_t)(row0    )*Vn + v] = o0;
            *(float2*)&out[(size_t)(row0 + 8)*Vn + v] = o1;
        }
    }
}

// ============================================================
extern "C" void kernel_launch(void* const* d_in, const int* in_sizes, int n_in,
                              void* d_out, int out_size) {
    const int*   tgt    = (const int*)d_in[0];
    const float* hidden = (const float*)d_in[1];
    const float* enc    = (const float*)d_in[2];
    const int*   mask   = (const int*)d_in[3];
    const float* emb    = (const float*)d_in[4];
    const float* Wa_enc = (const float*)d_in[5];
    const float* Wa_dec = (const float*)d_in[6];
    const float* ba     = (const float*)d_in[7];
    const float* v_att  = (const float*)d_in[8];
    const float* W_ih   = (const float*)d_in[9];
    const float* W_hh   = (const float*)d_in[10];
    const float* b_ih   = (const float*)d_in[11];
    const float* b_hh   = (const float*)d_in[12];
    const float* W_fc   = (const float*)d_in[13];
    const float* b_fc   = (const float*)d_in[14];

    float* out_pred = (float*)d_out;
    float* out_h    = nullptr;
    float* out_attn = nullptr;
    if (out_size >= Bn*Vn + Bn*Hn + Bn*Sn) {
        out_h    = out_pred + (size_t)Bn*Vn;
        out_attn = out_h    + (size_t)Bn*Hn;
    }

    k0_embed_dproj<<<Bn, 256>>>(tgt, hidden, emb, Wa_dec, ba);
    k1_energy<<<dim3(2, Bn), 256>>>(enc, Wa_enc, v_att, mask);
    k2_softmax_ctx<<<dim3(Bn, 2), 128>>>(enc, out_attn);
    k3_gates<<<dim3(48, 2), 256>>>(hidden, W_ih, W_hh, b_ih, b_hh);
    k3b_gru<<<128, 256>>>(hidden, out_h);
    k4_fc<<<250, 256>>>(W_fc, b_fc, out_pred);
}